// round 2
// baseline (speedup 1.0000x reference)
#include <cuda_runtime.h>
#include <math.h>

// Problem constants
#define BB   2
#define TT   2048
#define CCH  2048
#define HH   16
#define HKK  4
#define DD   128
#define MR   (BB*TT)          // 4096 rows

// ---------------------------------------------------------------------------
// Scratch (device globals; no allocation allowed)
// ---------------------------------------------------------------------------
__device__ float g_q[(size_t)BB*TT*HH*DD];    // (B,T,H*D) after RoPE
__device__ float g_k[(size_t)BB*TT*HKK*DD];   // (B,T,HK*D) after RoPE
__device__ float g_v[(size_t)BB*TT*HKK*DD];   // (B,T,HK*D)
__device__ float g_y[(size_t)BB*TT*CCH];      // attention output (B,T,C)

// ---------------------------------------------------------------------------
// Tiled fp32 GEMM: C[M,N] = A[M,K] * B[K,N], all row-major.
// BM=BN=128, BK=16, 256 threads, 8x8 per-thread micro-tile.
// MODE 0: plain store. MODE 1: RoPE epilogue (needs cos/sin). MODE 2: write
// transposed to (B,HK,T,D) layout (for k_write/v_write directly into d_out).
// ---------------------------------------------------------------------------
template<int MODE>
__global__ __launch_bounds__(256)
void gemm_kernel(const float* __restrict__ A, const float* __restrict__ Bw,
                 float* __restrict__ Cout, int M, int N, int K,
                 const float* __restrict__ cosT, const float* __restrict__ sinT)
{
    __shared__ float As[16][128];   // transposed A tile: As[k][m]
    __shared__ float Bs[16][128];   // Bs[k][n]

    const int tid = threadIdx.x;
    const int tx = tid & 15, ty = tid >> 4;
    const int m0 = blockIdx.y * 128;
    const int n0 = blockIdx.x * 128;

    float acc[2][2][4][4];
    #pragma unroll
    for (int ri=0;ri<2;ri++)
      #pragma unroll
      for (int ci=0;ci<2;ci++)
        #pragma unroll
        for (int i=0;i<4;i++)
          #pragma unroll
          for (int j=0;j<4;j++) acc[ri][ci][i][j] = 0.f;

    const int arow = tid >> 2;         // 0..63
    const int acol = (tid & 3) * 4;    // 0,4,8,12

    for (int k0 = 0; k0 < K; k0 += 16) {
        // Load A tile (128x16), store transposed
        #pragma unroll
        for (int r = 0; r < 2; r++) {
            int row = arow + r*64;
            float4 av = *reinterpret_cast<const float4*>(&A[(size_t)(m0+row)*K + k0 + acol]);
            As[acol+0][row] = av.x;
            As[acol+1][row] = av.y;
            As[acol+2][row] = av.z;
            As[acol+3][row] = av.w;
        }
        // Load B tile (16x128) straight
        #pragma unroll
        for (int r = 0; r < 2; r++) {
            int idx = tid + r*256;
            int brow = idx >> 5, bcol = (idx & 31) << 2;
            *reinterpret_cast<float4*>(&Bs[brow][bcol]) =
                *reinterpret_cast<const float4*>(&Bw[(size_t)(k0+brow)*N + n0 + bcol]);
        }
        __syncthreads();
        #pragma unroll
        for (int kk = 0; kk < 16; kk++) {
            float4 a0 = *reinterpret_cast<float4*>(&As[kk][ty*4]);
            float4 a1 = *reinterpret_cast<float4*>(&As[kk][64 + ty*4]);
            float4 b0 = *reinterpret_cast<float4*>(&Bs[kk][tx*4]);
            float4 b1 = *reinterpret_cast<float4*>(&Bs[kk][64 + tx*4]);
            float ar[2][4] = {{a0.x,a0.y,a0.z,a0.w},{a1.x,a1.y,a1.z,a1.w}};
            float br[2][4] = {{b0.x,b0.y,b0.z,b0.w},{b1.x,b1.y,b1.z,b1.w}};
            #pragma unroll
            for (int ri=0;ri<2;ri++)
              #pragma unroll
              for (int ci=0;ci<2;ci++)
                #pragma unroll
                for (int i=0;i<4;i++)
                  #pragma unroll
                  for (int j=0;j<4;j++)
                    acc[ri][ci][i][j] += ar[ri][i] * br[ci][j];
        }
        __syncthreads();
    }

    // Epilogue
    #pragma unroll
    for (int ri=0;ri<2;ri++) {
      #pragma unroll
      for (int i=0;i<4;i++) {
        int m = m0 + ri*64 + ty*4 + i;
        #pragma unroll
        for (int ci=0;ci<2;ci++) {
            int n = n0 + ci*64 + tx*4;
            float4 vv = make_float4(acc[ri][ci][i][0], acc[ri][ci][i][1],
                                    acc[ri][ci][i][2], acc[ri][ci][i][3]);
            if (MODE == 0) {
                *reinterpret_cast<float4*>(&Cout[(size_t)m*N + n]) = vv;
            } else if (MODE == 1) {
                int t  = m & (TT-1);
                int d  = n & (DD-1);
                int j0 = d >> 1;
                const float* cb = cosT + (size_t)t*(DD/2);
                const float* sb = sinT + (size_t)t*(DD/2);
                float c0 = cb[j0],   s0 = sb[j0];
                float c1 = cb[j0+1], s1 = sb[j0+1];
                float4 r;
                r.x = vv.x*c0 - vv.y*s0;
                r.y = vv.x*s0 + vv.y*c0;
                r.z = vv.z*c1 - vv.w*s1;
                r.w = vv.z*s1 + vv.w*c1;
                *reinterpret_cast<float4*>(&Cout[(size_t)m*N + n]) = r;
            } else {
                int b  = m >> 11;      // /TT
                int t  = m & (TT-1);
                int hk = n >> 7;       // /DD
                int d  = n & (DD-1);
                size_t off = (((size_t)(b*HKK + hk)*TT + t)*DD) + d;
                *reinterpret_cast<float4*>(&Cout[off]) = vv;
            }
        }
      }
    }
}

// ---------------------------------------------------------------------------
// Causal GQA flash attention, fp32. Grid: (T/64, H, B), 256 threads.
// Per block: Q tile 64 rows of head h; loop over K/V tiles of kv-head h/4.
// Dynamic smem: Qt[128][64] + Kt[128][64] + Vs[64][128] + Ss[64][72]
// ---------------------------------------------------------------------------
__global__ __launch_bounds__(256)
void attn_kernel(const float* __restrict__ q, const float* __restrict__ k,
                 const float* __restrict__ v, float* __restrict__ y)
{
    extern __shared__ float sm[];
    float* Qt = sm;            // [128][64]  (Qt[d][row])
    float* Kt = sm + 8192;     // [128][64]  (Kt[d][col])
    float* Vs = sm + 16384;    // [64][128]
    float* Ss = sm + 24576;    // [64][72]

    const int it = blockIdx.x;
    const int h  = blockIdx.y;
    const int b  = blockIdx.z;
    const int g  = h >> 2;       // kv head (NREP=4)
    const int t0 = it * 64;
    const int tid = threadIdx.x;
    const int tx = tid & 15, ty = tid >> 4;
    const float scale = 0.08838834764831845f;   // 1/sqrt(128)

    // Load Q tile transposed
    for (int e = tid; e < 64*32; e += 256) {
        int row = e >> 5;
        int c4  = (e & 31) << 2;
        float4 qv = *reinterpret_cast<const float4*>(
            &q[((size_t)(b*TT + t0 + row)*HH + h)*DD + c4]);
        Qt[(c4+0)*64 + row] = qv.x;
        Qt[(c4+1)*64 + row] = qv.y;
        Qt[(c4+2)*64 + row] = qv.z;
        Qt[(c4+3)*64 + row] = qv.w;
    }

    float m_i[4], l_i[4], o[4][8];
    #pragma unroll
    for (int i=0;i<4;i++) {
        m_i[i] = -INFINITY; l_i[i] = 0.f;
        #pragma unroll
        for (int j=0;j<8;j++) o[i][j] = 0.f;
    }

    for (int jt = 0; jt <= it; jt++) {
        const int s0 = jt * 64;
        __syncthreads();   // previous PV readers done before overwriting K/V/S
        for (int e = tid; e < 64*32; e += 256) {
            int row = e >> 5;
            int c4  = (e & 31) << 2;
            size_t base = ((size_t)(b*TT + s0 + row)*HKK + g)*DD + c4;
            float4 kv = *reinterpret_cast<const float4*>(&k[base]);
            Kt[(c4+0)*64 + row] = kv.x;
            Kt[(c4+1)*64 + row] = kv.y;
            Kt[(c4+2)*64 + row] = kv.z;
            Kt[(c4+3)*64 + row] = kv.w;
            *reinterpret_cast<float4*>(&Vs[row*128 + c4]) =
                *reinterpret_cast<const float4*>(&v[base]);
        }
        __syncthreads();

        // S = Q K^T (64x64), thread computes 4x4 at (ty*4, tx*4)
        float s[4][4];
        #pragma unroll
        for (int i=0;i<4;i++)
          #pragma unroll
          for (int j=0;j<4;j++) s[i][j] = 0.f;

        #pragma unroll 4
        for (int d = 0; d < 128; d++) {
            float4 a = *reinterpret_cast<float4*>(&Qt[d*64 + ty*4]);
            float4 bb = *reinterpret_cast<float4*>(&Kt[d*64 + tx*4]);
            float ar[4] = {a.x, a.y, a.z, a.w};
            float br[4] = {bb.x, bb.y, bb.z, bb.w};
            #pragma unroll
            for (int i=0;i<4;i++)
              #pragma unroll
              for (int j=0;j<4;j++)
                s[i][j] += ar[i] * br[j];
        }

        // Online softmax update
        const bool diag = (jt == it);
        #pragma unroll
        for (int i=0;i<4;i++) {
            const int trow = t0 + ty*4 + i;
            float ps[4];
            #pragma unroll
            for (int j=0;j<4;j++) {
                float sv = s[i][j] * scale;
                if (diag && (s0 + tx*4 + j) > trow) sv = -INFINITY;
                ps[j] = sv;
            }
            float rmax = fmaxf(fmaxf(ps[0],ps[1]), fmaxf(ps[2],ps[3]));
            #pragma unroll
            for (int msk=1; msk<16; msk<<=1)
                rmax = fmaxf(rmax, __shfl_xor_sync(0xffffffffu, rmax, msk));
            float m_new = fmaxf(m_i[i], rmax);
            float rsum = 0.f;
            #pragma unroll
            for (int j=0;j<4;j++) {
                float p = __expf(ps[j] - m_new);
                Ss[(ty*4+i)*72 + tx*4 + j] = p;
                rsum += p;
            }
            #pragma unroll
            for (int msk=1; msk<16; msk<<=1)
                rsum += __shfl_xor_sync(0xffffffffu, rsum, msk);
            float factor = __expf(m_i[i] - m_new);
            l_i[i] = l_i[i]*factor + rsum;
            m_i[i] = m_new;
            #pragma unroll
            for (int j=0;j<8;j++) o[i][j] *= factor;
        }
        __syncthreads();

        // O += P * V ; thread cols tx*8 .. tx*8+7
        for (int s4 = 0; s4 < 16; s4++) {
            float pb[4][4];
            #pragma unroll
            for (int i=0;i<4;i++) {
                float4 pv = *reinterpret_cast<float4*>(&Ss[(ty*4+i)*72 + s4*4]);
                pb[i][0]=pv.x; pb[i][1]=pv.y; pb[i][2]=pv.z; pb[i][3]=pv.w;
            }
            #pragma unroll
            for (int ss=0; ss<4; ss++) {
                float4 v0 = *reinterpret_cast<float4*>(&Vs[(s4*4+ss)*128 + tx*8]);
                float4 v1 = *reinterpret_cast<float4*>(&Vs[(s4*4+ss)*128 + tx*8 + 4]);
                #pragma unroll
                for (int i=0;i<4;i++) {
                    float p = pb[i][ss];
                    o[i][0] += p*v0.x; o[i][1] += p*v0.y;
                    o[i][2] += p*v0.z; o[i][3] += p*v0.w;
                    o[i][4] += p*v1.x; o[i][5] += p*v1.y;
                    o[i][6] += p*v1.z; o[i][7] += p*v1.w;
                }
            }
        }
    }

    // Normalize and write y (B,T,C) with C = H*D
    #pragma unroll
    for (int i=0;i<4;i++) {
        float inv = 1.f / l_i[i];
        int t = t0 + ty*4 + i;
        float4 w0 = make_float4(o[i][0]*inv, o[i][1]*inv, o[i][2]*inv, o[i][3]*inv);
        float4 w1 = make_float4(o[i][4]*inv, o[i][5]*inv, o[i][6]*inv, o[i][7]*inv);
        size_t base = ((size_t)(b*TT + t)*HH + h)*DD + tx*8;
        *reinterpret_cast<float4*>(&y[base])     = w0;
        *reinterpret_cast<float4*>(&y[base + 4]) = w1;
    }
}

// ---------------------------------------------------------------------------
// Launch
// ---------------------------------------------------------------------------
extern "C" void kernel_launch(void* const* d_in, const int* in_sizes, int n_in,
                              void* d_out, int out_size)
{
    const float* x      = (const float*)d_in[0];
    const float* w_q    = (const float*)d_in[1];
    const float* w_k    = (const float*)d_in[2];
    const float* w_v    = (const float*)d_in[3];
    const float* w_proj = (const float*)d_in[4];
    const float* w_dk   = (const float*)d_in[5];
    const float* w_dv   = (const float*)d_in[6];
    const float* fcos   = (const float*)d_in[7];
    const float* fsin   = (const float*)d_in[8];

    float* out    = (float*)d_out;
    float* out_y  = out;                                   // B*T*C
    float* out_kw = out + (size_t)BB*TT*CCH;               // B*HK*T*D
    float* out_vw = out_kw + (size_t)BB*HKK*TT*DD;

    // One-time setup (deterministic; no work skipped — every call enqueues
    // the same launches below).
    static float *pq = nullptr, *pk = nullptr, *pv = nullptr, *py = nullptr;
    static int smem_attn = 0;
    if (!pq) {
        cudaGetSymbolAddress((void**)&pq, g_q);
        cudaGetSymbolAddress((void**)&pk, g_k);
        cudaGetSymbolAddress((void**)&pv, g_v);
        cudaGetSymbolAddress((void**)&py, g_y);
        smem_attn = (8192 + 8192 + 8192 + 64*72) * sizeof(float); // 116736
        cudaFuncSetAttribute(attn_kernel,
                             cudaFuncAttributeMaxDynamicSharedMemorySize, smem_attn);
    }

    dim3 blk(256);
    // Projections
    gemm_kernel<1><<<dim3(CCH/128,     MR/128), blk>>>(x, w_q,  pq,     MR, CCH,     CCH, fcos, fsin);
    gemm_kernel<1><<<dim3(HKK*DD/128,  MR/128), blk>>>(x, w_k,  pk,     MR, HKK*DD,  CCH, fcos, fsin);
    gemm_kernel<0><<<dim3(HKK*DD/128,  MR/128), blk>>>(x, w_v,  pv,     MR, HKK*DD,  CCH, 0, 0);
    gemm_kernel<2><<<dim3(HKK*DD/128,  MR/128), blk>>>(x, w_dk, out_kw, MR, HKK*DD,  CCH, 0, 0);
    gemm_kernel<2><<<dim3(HKK*DD/128,  MR/128), blk>>>(x, w_dv, out_vw, MR, HKK*DD,  CCH, 0, 0);
    // Attention
    attn_kernel<<<dim3(TT/64, HH, BB), blk, smem_attn>>>(pq, pk, pv, py);
    // Output projection
    gemm_kernel<0><<<dim3(CCH/128, MR/128), blk>>>(py, w_proj, out_y, MR, CCH, CCH, 0, 0);
}

// round 6
// speedup vs baseline: 1.4017x; 1.4017x over previous
#include <cuda_runtime.h>
#include <cuda_bf16.h>
#include <math.h>
#include <stdint.h>

// Problem constants
#define BB   2
#define TT   2048
#define CCH  2048
#define HH   16
#define HKK  4
#define DD   128
#define MR   (BB*TT)          // 4096 rows
#define KGEMM 2048            // K of every GEMM here

// Weight scratch offsets (bf16 transposed [N][K])
#define WQ_OFF  0u
#define WK_OFF  4194304u
#define WV_OFF  5242880u
#define WDK_OFF 6291456u
#define WDV_OFF 7340032u
#define WP_OFF  8388608u
#define WTOT    12582912u

// ---------------------------------------------------------------------------
// Scratch (device globals; no allocation allowed)
// ---------------------------------------------------------------------------
__device__ float g_q[(size_t)BB*TT*HH*DD];      // (B,T,H*D) after RoPE (fp32)
__device__ float g_k[(size_t)BB*TT*HKK*DD];     // (B,T,HK*D) after RoPE
__device__ float g_v[(size_t)BB*TT*HKK*DD];     // (B,T,HK*D)
__device__ __nv_bfloat16 g_xh[(size_t)MR*CCH], g_xl[(size_t)MR*CCH];
__device__ __nv_bfloat16 g_yh[(size_t)MR*CCH], g_yl[(size_t)MR*CCH];
__device__ __nv_bfloat16 g_wh[WTOT], g_wl[WTOT];

// ---------------------------------------------------------------------------
// mma.sync m16n8k16 bf16 (legacy tensor-core path; compiles at compute_100)
// ---------------------------------------------------------------------------
__device__ __forceinline__ void mma16816(float* c, const uint32_t* a, const uint32_t* b)
{
    asm volatile(
        "mma.sync.aligned.m16n8k16.row.col.f32.bf16.bf16.f32 "
        "{%0,%1,%2,%3}, {%4,%5,%6,%7}, {%8,%9}, {%0,%1,%2,%3};\n"
        : "+f"(c[0]), "+f"(c[1]), "+f"(c[2]), "+f"(c[3])
        : "r"(a[0]), "r"(a[1]), "r"(a[2]), "r"(a[3]), "r"(b[0]), "r"(b[1]));
}

// ---------------------------------------------------------------------------
// Split fp32 -> bf16 hi/lo (elementwise, vectorized)
// ---------------------------------------------------------------------------
__global__ __launch_bounds__(256)
void split_f32(const float* __restrict__ s, __nv_bfloat16* __restrict__ dh,
               __nv_bfloat16* __restrict__ dl, int n4)
{
    int i = blockIdx.x * blockDim.x + threadIdx.x;
    if (i >= n4) return;
    float4 v = reinterpret_cast<const float4*>(s)[i];
    __nv_bfloat162 h0 = __floats2bfloat162_rn(v.x, v.y);
    __nv_bfloat162 h1 = __floats2bfloat162_rn(v.z, v.w);
    __nv_bfloat162 l0 = __floats2bfloat162_rn(v.x - __bfloat162float(h0.x),
                                              v.y - __bfloat162float(h0.y));
    __nv_bfloat162 l1 = __floats2bfloat162_rn(v.z - __bfloat162float(h1.x),
                                              v.w - __bfloat162float(h1.y));
    uint2 hp = make_uint2(*reinterpret_cast<uint32_t*>(&h0), *reinterpret_cast<uint32_t*>(&h1));
    uint2 lp = make_uint2(*reinterpret_cast<uint32_t*>(&l0), *reinterpret_cast<uint32_t*>(&l1));
    reinterpret_cast<uint2*>(dh)[i] = hp;
    reinterpret_cast<uint2*>(dl)[i] = lp;
}

// ---------------------------------------------------------------------------
// Transpose W[K][N] fp32 -> Wt[N][K] bf16 hi/lo. Block (32,8), grid (N/32,K/32).
// ---------------------------------------------------------------------------
__global__ __launch_bounds__(256)
void transpose_w(const float* __restrict__ W, __nv_bfloat16* __restrict__ Th,
                 __nv_bfloat16* __restrict__ Tl, int K, int N)
{
    __shared__ float tile[32][33];
    const int n0 = blockIdx.x * 32, k0 = blockIdx.y * 32;
    const int tx = threadIdx.x, ty = threadIdx.y;
    #pragma unroll
    for (int i = 0; i < 4; i++)
        tile[ty + i * 8][tx] = W[(size_t)(k0 + ty + i * 8) * N + n0 + tx];
    __syncthreads();
    #pragma unroll
    for (int i = 0; i < 4; i++) {
        int n = ty + i * 8;
        float v = tile[tx][n];
        __nv_bfloat16 h = __float2bfloat16(v);
        __nv_bfloat16 l = __float2bfloat16(v - __bfloat162float(h));
        size_t off = (size_t)(n0 + n) * K + k0 + tx;
        Th[off] = h;
        Tl[off] = l;
    }
}

// ---------------------------------------------------------------------------
// HMMA GEMM: C[4096,N] = A[4096,2048]*W[2048,N], A/B given as bf16 hi/lo,
// A row-major [M][K], B transposed K-major [N][K]. bf16x3 split accumulation.
// CTA: 128x128 tile, 8 warps (2m x 4n), warp 64x32, BK=32.
// MODE 0: plain fp32 store. MODE 1: RoPE. MODE 2: (B,HK,T,D) transposed store.
// ---------------------------------------------------------------------------
#define SA 40   // padded smem row stride in bf16 (80B, conflict-free)

template<int MODE>
__global__ __launch_bounds__(256, 2)
void gemm_mma(const __nv_bfloat16* __restrict__ AH, const __nv_bfloat16* __restrict__ AL,
              const __nv_bfloat16* __restrict__ BH, const __nv_bfloat16* __restrict__ BL,
              float* __restrict__ Cout, int N,
              const float* __restrict__ cosT, const float* __restrict__ sinT)
{
    __shared__ __nv_bfloat16 sAH[128 * SA], sAL[128 * SA];
    __shared__ __nv_bfloat16 sBH[128 * SA], sBL[128 * SA];

    const int tid = threadIdx.x;
    const int wid = tid >> 5, lane = tid & 31;
    const int g = lane >> 2, tig = lane & 3;
    const int wm = wid >> 2, wn = wid & 3;       // 2 x 4 warp grid
    const int m0 = blockIdx.y * 128;
    const int n0 = blockIdx.x * 128;

    float acc[4][4][4];
    #pragma unroll
    for (int mt = 0; mt < 4; mt++)
        #pragma unroll
        for (int nt = 0; nt < 4; nt++)
            #pragma unroll
            for (int e = 0; e < 4; e++) acc[mt][nt][e] = 0.f;

    for (int kc = 0; kc < KGEMM / 32; kc++) {
        const int k0 = kc * 32;
        #pragma unroll
        for (int it = 0; it < 2; it++) {
            int c = tid + it * 256;
            int row = c >> 2, part = c & 3;
            size_t ga = (size_t)(m0 + row) * KGEMM + k0 + part * 8;
            size_t gb = (size_t)(n0 + row) * KGEMM + k0 + part * 8;
            int so = row * SA + part * 8;
            *reinterpret_cast<uint4*>(&sAH[so]) = *reinterpret_cast<const uint4*>(&AH[ga]);
            *reinterpret_cast<uint4*>(&sAL[so]) = *reinterpret_cast<const uint4*>(&AL[ga]);
            *reinterpret_cast<uint4*>(&sBH[so]) = *reinterpret_cast<const uint4*>(&BH[gb]);
            *reinterpret_cast<uint4*>(&sBL[so]) = *reinterpret_cast<const uint4*>(&BL[gb]);
        }
        __syncthreads();

        #pragma unroll
        for (int ks = 0; ks < 2; ks++) {
            const int kcol = ks * 16 + 2 * tig;
            uint32_t bh[4][2], bl[4][2];
            #pragma unroll
            for (int nt = 0; nt < 4; nt++) {
                int brow = (wn * 32 + nt * 8 + g) * SA;
                bh[nt][0] = *reinterpret_cast<const uint32_t*>(&sBH[brow + kcol]);
                bh[nt][1] = *reinterpret_cast<const uint32_t*>(&sBH[brow + kcol + 8]);
                bl[nt][0] = *reinterpret_cast<const uint32_t*>(&sBL[brow + kcol]);
                bl[nt][1] = *reinterpret_cast<const uint32_t*>(&sBL[brow + kcol + 8]);
            }
            uint32_t af[4][4];
            #pragma unroll
            for (int mt = 0; mt < 4; mt++) {
                int ar = (wm * 64 + mt * 16 + g) * SA;
                af[mt][0] = *reinterpret_cast<const uint32_t*>(&sAH[ar + kcol]);
                af[mt][1] = *reinterpret_cast<const uint32_t*>(&sAH[ar + 8 * SA + kcol]);
                af[mt][2] = *reinterpret_cast<const uint32_t*>(&sAH[ar + kcol + 8]);
                af[mt][3] = *reinterpret_cast<const uint32_t*>(&sAH[ar + 8 * SA + kcol + 8]);
            }
            #pragma unroll
            for (int mt = 0; mt < 4; mt++)
                #pragma unroll
                for (int nt = 0; nt < 4; nt++) {
                    mma16816(acc[mt][nt], af[mt], bh[nt]);
                    mma16816(acc[mt][nt], af[mt], bl[nt]);
                }
            #pragma unroll
            for (int mt = 0; mt < 4; mt++) {
                int ar = (wm * 64 + mt * 16 + g) * SA;
                af[mt][0] = *reinterpret_cast<const uint32_t*>(&sAL[ar + kcol]);
                af[mt][1] = *reinterpret_cast<const uint32_t*>(&sAL[ar + 8 * SA + kcol]);
                af[mt][2] = *reinterpret_cast<const uint32_t*>(&sAL[ar + kcol + 8]);
                af[mt][3] = *reinterpret_cast<const uint32_t*>(&sAL[ar + 8 * SA + kcol + 8]);
            }
            #pragma unroll
            for (int mt = 0; mt < 4; mt++)
                #pragma unroll
                for (int nt = 0; nt < 4; nt++)
                    mma16816(acc[mt][nt], af[mt], bh[nt]);
        }
        __syncthreads();
    }

    // Epilogue: thread owns pairs (row, n..n+1) and (row+8, n..n+1) per tile
    #pragma unroll
    for (int mt = 0; mt < 4; mt++) {
        const int r0 = m0 + wm * 64 + mt * 16 + g;
        #pragma unroll
        for (int nt = 0; nt < 4; nt++) {
            const int n = n0 + wn * 32 + nt * 8 + 2 * tig;
            #pragma unroll
            for (int half = 0; half < 2; half++) {
                const int m = r0 + half * 8;
                float e = acc[mt][nt][half * 2 + 0];
                float o = acc[mt][nt][half * 2 + 1];
                if (MODE == 1) {
                    int t = m & (TT - 1);
                    int j0 = (n & (DD - 1)) >> 1;
                    float cc = cosT[(size_t)t * (DD / 2) + j0];
                    float ss = sinT[(size_t)t * (DD / 2) + j0];
                    float e2 = e * cc - o * ss;
                    o = e * ss + o * cc;
                    e = e2;
                }
                float2 vv = make_float2(e, o);
                if (MODE == 2) {
                    int b = m >> 11, t = m & (TT - 1);
                    int hk = n >> 7, d = n & (DD - 1);
                    *reinterpret_cast<float2*>(
                        &Cout[(((size_t)(b * HKK + hk) * TT + t) * DD) + d]) = vv;
                } else {
                    *reinterpret_cast<float2*>(&Cout[(size_t)m * N + n]) = vv;
                }
            }
        }
    }
}

// ---------------------------------------------------------------------------
// Causal GQA flash attention, fp32; writes y as bf16 hi/lo for the out-proj.
// ---------------------------------------------------------------------------
__global__ __launch_bounds__(256)
void attn_kernel(const float* __restrict__ q, const float* __restrict__ k,
                 const float* __restrict__ v,
                 __nv_bfloat16* __restrict__ yh, __nv_bfloat16* __restrict__ yl)
{
    extern __shared__ float sm[];
    float* Qt = sm;            // [128][64]
    float* Kt = sm + 8192;     // [128][64]
    float* Vs = sm + 16384;    // [64][128]
    float* Ss = sm + 24576;    // [64][72]

    const int it = blockIdx.x;
    const int hd = blockIdx.y;
    const int b  = blockIdx.z;
    const int gk = hd >> 2;
    const int t0 = it * 64;
    const int tid = threadIdx.x;
    const int tx = tid & 15, ty = tid >> 4;
    const float scale = 0.08838834764831845f;

    for (int e = tid; e < 64 * 32; e += 256) {
        int row = e >> 5;
        int c4  = (e & 31) << 2;
        float4 qv = *reinterpret_cast<const float4*>(
            &q[((size_t)(b * TT + t0 + row) * HH + hd) * DD + c4]);
        Qt[(c4 + 0) * 64 + row] = qv.x;
        Qt[(c4 + 1) * 64 + row] = qv.y;
        Qt[(c4 + 2) * 64 + row] = qv.z;
        Qt[(c4 + 3) * 64 + row] = qv.w;
    }

    float m_i[4], l_i[4], o[4][8];
    #pragma unroll
    for (int i = 0; i < 4; i++) {
        m_i[i] = -INFINITY; l_i[i] = 0.f;
        #pragma unroll
        for (int j = 0; j < 8; j++) o[i][j] = 0.f;
    }

    for (int jt = 0; jt <= it; jt++) {
        const int s0 = jt * 64;
        __syncthreads();
        for (int e = tid; e < 64 * 32; e += 256) {
            int row = e >> 5;
            int c4  = (e & 31) << 2;
            size_t base = ((size_t)(b * TT + s0 + row) * HKK + gk) * DD + c4;
            float4 kv = *reinterpret_cast<const float4*>(&k[base]);
            Kt[(c4 + 0) * 64 + row] = kv.x;
            Kt[(c4 + 1) * 64 + row] = kv.y;
            Kt[(c4 + 2) * 64 + row] = kv.z;
            Kt[(c4 + 3) * 64 + row] = kv.w;
            *reinterpret_cast<float4*>(&Vs[row * 128 + c4]) =
                *reinterpret_cast<const float4*>(&v[base]);
        }
        __syncthreads();

        float s[4][4];
        #pragma unroll
        for (int i = 0; i < 4; i++)
            #pragma unroll
            for (int j = 0; j < 4; j++) s[i][j] = 0.f;

        #pragma unroll 4
        for (int d = 0; d < 128; d++) {
            float4 a  = *reinterpret_cast<float4*>(&Qt[d * 64 + ty * 4]);
            float4 bb = *reinterpret_cast<float4*>(&Kt[d * 64 + tx * 4]);
            float ar[4] = {a.x, a.y, a.z, a.w};
            float br[4] = {bb.x, bb.y, bb.z, bb.w};
            #pragma unroll
            for (int i = 0; i < 4; i++)
                #pragma unroll
                for (int j = 0; j < 4; j++)
                    s[i][j] += ar[i] * br[j];
        }

        const bool diag = (jt == it);
        #pragma unroll
        for (int i = 0; i < 4; i++) {
            const int trow = t0 + ty * 4 + i;
            float ps[4];
            #pragma unroll
            for (int j = 0; j < 4; j++) {
                float sv = s[i][j] * scale;
                if (diag && (s0 + tx * 4 + j) > trow) sv = -INFINITY;
                ps[j] = sv;
            }
            float rmax = fmaxf(fmaxf(ps[0], ps[1]), fmaxf(ps[2], ps[3]));
            #pragma unroll
            for (int msk = 1; msk < 16; msk <<= 1)
                rmax = fmaxf(rmax, __shfl_xor_sync(0xffffffffu, rmax, msk));
            float m_new = fmaxf(m_i[i], rmax);
            float rsum = 0.f;
            #pragma unroll
            for (int j = 0; j < 4; j++) {
                float p = __expf(ps[j] - m_new);
                Ss[(ty * 4 + i) * 72 + tx * 4 + j] = p;
                rsum += p;
            }
            #pragma unroll
            for (int msk = 1; msk < 16; msk <<= 1)
                rsum += __shfl_xor_sync(0xffffffffu, rsum, msk);
            float factor = __expf(m_i[i] - m_new);
            l_i[i] = l_i[i] * factor + rsum;
            m_i[i] = m_new;
            #pragma unroll
            for (int j = 0; j < 8; j++) o[i][j] *= factor;
        }
        __syncthreads();

        for (int s4 = 0; s4 < 16; s4++) {
            float pb[4][4];
            #pragma unroll
            for (int i = 0; i < 4; i++) {
                float4 pv = *reinterpret_cast<float4*>(&Ss[(ty * 4 + i) * 72 + s4 * 4]);
                pb[i][0] = pv.x; pb[i][1] = pv.y; pb[i][2] = pv.z; pb[i][3] = pv.w;
            }
            #pragma unroll
            for (int ss = 0; ss < 4; ss++) {
                float4 v0 = *reinterpret_cast<float4*>(&Vs[(s4 * 4 + ss) * 128 + tx * 8]);
                float4 v1 = *reinterpret_cast<float4*>(&Vs[(s4 * 4 + ss) * 128 + tx * 8 + 4]);
                #pragma unroll
                for (int i = 0; i < 4; i++) {
                    float p = pb[i][ss];
                    o[i][0] += p * v0.x; o[i][1] += p * v0.y;
                    o[i][2] += p * v0.z; o[i][3] += p * v0.w;
                    o[i][4] += p * v1.x; o[i][5] += p * v1.y;
                    o[i][6] += p * v1.z; o[i][7] += p * v1.w;
                }
            }
        }
    }

    #pragma unroll
    for (int i = 0; i < 4; i++) {
        float inv = 1.f / l_i[i];
        int t = t0 + ty * 4 + i;
        uint32_t hp[4], lp[4];
        #pragma unroll
        for (int j = 0; j < 4; j++) {
            float a = o[i][2 * j] * inv, bbf = o[i][2 * j + 1] * inv;
            __nv_bfloat162 h = __floats2bfloat162_rn(a, bbf);
            __nv_bfloat162 l = __floats2bfloat162_rn(a - __bfloat162float(h.x),
                                                     bbf - __bfloat162float(h.y));
            hp[j] = *reinterpret_cast<uint32_t*>(&h);
            lp[j] = *reinterpret_cast<uint32_t*>(&l);
        }
        size_t base = ((size_t)(b * TT + t) * HH + hd) * DD + tx * 8;
        *reinterpret_cast<uint4*>(&yh[base]) = make_uint4(hp[0], hp[1], hp[2], hp[3]);
        *reinterpret_cast<uint4*>(&yl[base]) = make_uint4(lp[0], lp[1], lp[2], lp[3]);
    }
}

// ---------------------------------------------------------------------------
// Launch
// ---------------------------------------------------------------------------
extern "C" void kernel_launch(void* const* d_in, const int* in_sizes, int n_in,
                              void* d_out, int out_size)
{
    const float* x      = (const float*)d_in[0];
    const float* w_q    = (const float*)d_in[1];
    const float* w_k    = (const float*)d_in[2];
    const float* w_v    = (const float*)d_in[3];
    const float* w_proj = (const float*)d_in[4];
    const float* w_dk   = (const float*)d_in[5];
    const float* w_dv   = (const float*)d_in[6];
    const float* fcos   = (const float*)d_in[7];
    const float* fsin   = (const float*)d_in[8];

    float* out    = (float*)d_out;
    float* out_y  = out;
    float* out_kw = out + (size_t)BB * TT * CCH;
    float* out_vw = out_kw + (size_t)BB * HKK * TT * DD;

    static float *pq = nullptr, *pk = nullptr, *pv = nullptr;
    static __nv_bfloat16 *xh, *xl, *yh, *yl, *wh, *wl;
    static int smem_attn = 0;
    if (!pq) {
        cudaGetSymbolAddress((void**)&pq, g_q);
        cudaGetSymbolAddress((void**)&pk, g_k);
        cudaGetSymbolAddress((void**)&pv, g_v);
        cudaGetSymbolAddress((void**)&xh, g_xh);
        cudaGetSymbolAddress((void**)&xl, g_xl);
        cudaGetSymbolAddress((void**)&yh, g_yh);
        cudaGetSymbolAddress((void**)&yl, g_yl);
        cudaGetSymbolAddress((void**)&wh, g_wh);
        cudaGetSymbolAddress((void**)&wl, g_wl);
        smem_attn = (8192 + 8192 + 8192 + 64 * 72) * sizeof(float);
        cudaFuncSetAttribute(attn_kernel,
                             cudaFuncAttributeMaxDynamicSharedMemorySize, smem_attn);
    }

    // 1) split x into bf16 hi/lo
    split_f32<<<(MR * CCH / 4 + 255) / 256, 256>>>(x, xh, xl, MR * CCH / 4);
    // 2) transpose + split weights
    dim3 tb(32, 8);
    transpose_w<<<dim3(CCH / 32, CCH / 32), tb>>>(w_q,    wh + WQ_OFF,  wl + WQ_OFF,  CCH, CCH);
    transpose_w<<<dim3(512 / 32, CCH / 32), tb>>>(w_k,    wh + WK_OFF,  wl + WK_OFF,  CCH, 512);
    transpose_w<<<dim3(512 / 32, CCH / 32), tb>>>(w_v,    wh + WV_OFF,  wl + WV_OFF,  CCH, 512);
    transpose_w<<<dim3(512 / 32, CCH / 32), tb>>>(w_dk,   wh + WDK_OFF, wl + WDK_OFF, CCH, 512);
    transpose_w<<<dim3(512 / 32, CCH / 32), tb>>>(w_dv,   wh + WDV_OFF, wl + WDV_OFF, CCH, 512);
    transpose_w<<<dim3(CCH / 32, CCH / 32), tb>>>(w_proj, wh + WP_OFF,  wl + WP_OFF,  CCH, CCH);

    dim3 blk(256);
    const int MT = MR / 128;   // 32 m-tiles
    // 3) projections (HMMA bf16x3)
    gemm_mma<1><<<dim3(16, MT), blk>>>(xh, xl, wh + WQ_OFF,  wl + WQ_OFF,  pq,     CCH, fcos, fsin);
    gemm_mma<1><<<dim3(4,  MT), blk>>>(xh, xl, wh + WK_OFF,  wl + WK_OFF,  pk,     512, fcos, fsin);
    gemm_mma<0><<<dim3(4,  MT), blk>>>(xh, xl, wh + WV_OFF,  wl + WV_OFF,  pv,     512, 0, 0);
    gemm_mma<2><<<dim3(4,  MT), blk>>>(xh, xl, wh + WDK_OFF, wl + WDK_OFF, out_kw, 512, 0, 0);
    gemm_mma<2><<<dim3(4,  MT), blk>>>(xh, xl, wh + WDV_OFF, wl + WDV_OFF, out_vw, 512, 0, 0);
    // 4) attention (fp32 SIMT) -> y bf16 hi/lo
    attn_kernel<<<dim3(TT / 64, HH, BB), blk, smem_attn>>>(pq, pk, pv, yh, yl);
    // 5) output projection
    gemm_mma<0><<<dim3(16, MT), blk>>>(yh, yl, wh + WP_OFF, wl + WP_OFF, out_y, CCH, 0, 0);
}

// round 9
// speedup vs baseline: 2.6417x; 1.8846x over previous
#include <cuda_runtime.h>
#include <cuda_bf16.h>
#include <math.h>
#include <stdint.h>

// Problem constants
#define BB   2
#define TT   2048
#define CCH  2048
#define HH   16
#define HKK  4
#define DD   128
#define MR   (BB*TT)          // 4096 rows
#define KGEMM 2048            // K of every GEMM here

// Weight scratch offsets (bf16 transposed [N][K])
#define WQ_OFF  0u
#define WK_OFF  4194304u
#define WV_OFF  5242880u
#define WDK_OFF 6291456u
#define WDV_OFF 7340032u
#define WP_OFF  8388608u
#define WTOT    12582912u

// ---------------------------------------------------------------------------
// Scratch (device globals; no allocation allowed)
// ---------------------------------------------------------------------------
__device__ float g_q[(size_t)BB*TT*HH*DD];      // (B,T,H*D) after RoPE (fp32)
__device__ float g_k[(size_t)BB*TT*HKK*DD];     // (B,T,HK*D) after RoPE
__device__ float g_v[(size_t)BB*TT*HKK*DD];     // (B,T,HK*D)
__device__ __nv_bfloat16 g_xh[(size_t)MR*CCH], g_xl[(size_t)MR*CCH];
__device__ __nv_bfloat16 g_yh[(size_t)MR*CCH], g_yl[(size_t)MR*CCH];
__device__ __nv_bfloat16 g_wh[WTOT], g_wl[WTOT];

// ---------------------------------------------------------------------------
// mma.sync m16n8k16 bf16
// ---------------------------------------------------------------------------
__device__ __forceinline__ void mma16816(float* c, const uint32_t* a, const uint32_t* b)
{
    asm volatile(
        "mma.sync.aligned.m16n8k16.row.col.f32.bf16.bf16.f32 "
        "{%0,%1,%2,%3}, {%4,%5,%6,%7}, {%8,%9}, {%0,%1,%2,%3};\n"
        : "+f"(c[0]), "+f"(c[1]), "+f"(c[2]), "+f"(c[3])
        : "r"(a[0]), "r"(a[1]), "r"(a[2]), "r"(a[3]), "r"(b[0]), "r"(b[1]));
}

__device__ __forceinline__ uint32_t pack_hi2(float a, float b)
{
    __nv_bfloat162 h = __floats2bfloat162_rn(a, b);
    return *reinterpret_cast<uint32_t*>(&h);
}
__device__ __forceinline__ uint32_t pack_lo2(float a, float b, uint32_t hi)
{
    __nv_bfloat162 h = *reinterpret_cast<__nv_bfloat162*>(&hi);
    __nv_bfloat162 l = __floats2bfloat162_rn(a - __bfloat162float(h.x),
                                             b - __bfloat162float(h.y));
    return *reinterpret_cast<uint32_t*>(&l);
}

// ---------------------------------------------------------------------------
// Split fp32 -> bf16 hi/lo (elementwise, vectorized)
// ---------------------------------------------------------------------------
__global__ __launch_bounds__(256)
void split_f32(const float* __restrict__ s, __nv_bfloat16* __restrict__ dh,
               __nv_bfloat16* __restrict__ dl, int n4)
{
    int i = blockIdx.x * blockDim.x + threadIdx.x;
    if (i >= n4) return;
    float4 v = reinterpret_cast<const float4*>(s)[i];
    uint32_t h0 = pack_hi2(v.x, v.y), h1 = pack_hi2(v.z, v.w);
    uint32_t l0 = pack_lo2(v.x, v.y, h0), l1 = pack_lo2(v.z, v.w, h1);
    reinterpret_cast<uint2*>(dh)[i] = make_uint2(h0, h1);
    reinterpret_cast<uint2*>(dl)[i] = make_uint2(l0, l1);
}

// ---------------------------------------------------------------------------
// Transpose W[K][N] fp32 -> Wt[N][K] bf16 hi/lo. Block (32,8), grid (N/32,K/32).
// ---------------------------------------------------------------------------
__global__ __launch_bounds__(256)
void transpose_w(const float* __restrict__ W, __nv_bfloat16* __restrict__ Th,
                 __nv_bfloat16* __restrict__ Tl, int K, int N)
{
    __shared__ float tile[32][33];
    const int n0 = blockIdx.x * 32, k0 = blockIdx.y * 32;
    const int tx = threadIdx.x, ty = threadIdx.y;
    #pragma unroll
    for (int i = 0; i < 4; i++)
        tile[ty + i * 8][tx] = W[(size_t)(k0 + ty + i * 8) * N + n0 + tx];
    __syncthreads();
    #pragma unroll
    for (int i = 0; i < 4; i++) {
        int n = ty + i * 8;
        float v = tile[tx][n];
        __nv_bfloat16 h = __float2bfloat16(v);
        __nv_bfloat16 l = __float2bfloat16(v - __bfloat162float(h));
        size_t off = (size_t)(n0 + n) * K + k0 + tx;
        Th[off] = h;
        Tl[off] = l;
    }
}

// ---------------------------------------------------------------------------
// HMMA GEMM (unchanged from R6; passes at 3517us total)
// ---------------------------------------------------------------------------
#define SA 40

template<int MODE>
__global__ __launch_bounds__(256, 2)
void gemm_mma(const __nv_bfloat16* __restrict__ AH, const __nv_bfloat16* __restrict__ AL,
              const __nv_bfloat16* __restrict__ BH, const __nv_bfloat16* __restrict__ BL,
              float* __restrict__ Cout, int N,
              const float* __restrict__ cosT, const float* __restrict__ sinT)
{
    __shared__ __nv_bfloat16 sAH[128 * SA], sAL[128 * SA];
    __shared__ __nv_bfloat16 sBH[128 * SA], sBL[128 * SA];

    const int tid = threadIdx.x;
    const int wid = tid >> 5, lane = tid & 31;
    const int g = lane >> 2, tig = lane & 3;
    const int wm = wid >> 2, wn = wid & 3;
    const int m0 = blockIdx.y * 128;
    const int n0 = blockIdx.x * 128;

    float acc[4][4][4];
    #pragma unroll
    for (int mt = 0; mt < 4; mt++)
        #pragma unroll
        for (int nt = 0; nt < 4; nt++)
            #pragma unroll
            for (int e = 0; e < 4; e++) acc[mt][nt][e] = 0.f;

    for (int kc = 0; kc < KGEMM / 32; kc++) {
        const int k0 = kc * 32;
        #pragma unroll
        for (int it = 0; it < 2; it++) {
            int c = tid + it * 256;
            int row = c >> 2, part = c & 3;
            size_t ga = (size_t)(m0 + row) * KGEMM + k0 + part * 8;
            size_t gb = (size_t)(n0 + row) * KGEMM + k0 + part * 8;
            int so = row * SA + part * 8;
            *reinterpret_cast<uint4*>(&sAH[so]) = *reinterpret_cast<const uint4*>(&AH[ga]);
            *reinterpret_cast<uint4*>(&sAL[so]) = *reinterpret_cast<const uint4*>(&AL[ga]);
            *reinterpret_cast<uint4*>(&sBH[so]) = *reinterpret_cast<const uint4*>(&BH[gb]);
            *reinterpret_cast<uint4*>(&sBL[so]) = *reinterpret_cast<const uint4*>(&BL[gb]);
        }
        __syncthreads();

        #pragma unroll
        for (int ks = 0; ks < 2; ks++) {
            const int kcol = ks * 16 + 2 * tig;
            uint32_t bh[4][2], bl[4][2];
            #pragma unroll
            for (int nt = 0; nt < 4; nt++) {
                int brow = (wn * 32 + nt * 8 + g) * SA;
                bh[nt][0] = *reinterpret_cast<const uint32_t*>(&sBH[brow + kcol]);
                bh[nt][1] = *reinterpret_cast<const uint32_t*>(&sBH[brow + kcol + 8]);
                bl[nt][0] = *reinterpret_cast<const uint32_t*>(&sBL[brow + kcol]);
                bl[nt][1] = *reinterpret_cast<const uint32_t*>(&sBL[brow + kcol + 8]);
            }
            uint32_t af[4][4];
            #pragma unroll
            for (int mt = 0; mt < 4; mt++) {
                int ar = (wm * 64 + mt * 16 + g) * SA;
                af[mt][0] = *reinterpret_cast<const uint32_t*>(&sAH[ar + kcol]);
                af[mt][1] = *reinterpret_cast<const uint32_t*>(&sAH[ar + 8 * SA + kcol]);
                af[mt][2] = *reinterpret_cast<const uint32_t*>(&sAH[ar + kcol + 8]);
                af[mt][3] = *reinterpret_cast<const uint32_t*>(&sAH[ar + 8 * SA + kcol + 8]);
            }
            #pragma unroll
            for (int mt = 0; mt < 4; mt++)
                #pragma unroll
                for (int nt = 0; nt < 4; nt++) {
                    mma16816(acc[mt][nt], af[mt], bh[nt]);
                    mma16816(acc[mt][nt], af[mt], bl[nt]);
                }
            #pragma unroll
            for (int mt = 0; mt < 4; mt++) {
                int ar = (wm * 64 + mt * 16 + g) * SA;
                af[mt][0] = *reinterpret_cast<const uint32_t*>(&sAL[ar + kcol]);
                af[mt][1] = *reinterpret_cast<const uint32_t*>(&sAL[ar + 8 * SA + kcol]);
                af[mt][2] = *reinterpret_cast<const uint32_t*>(&sAL[ar + kcol + 8]);
                af[mt][3] = *reinterpret_cast<const uint32_t*>(&sAL[ar + 8 * SA + kcol + 8]);
            }
            #pragma unroll
            for (int mt = 0; mt < 4; mt++)
                #pragma unroll
                for (int nt = 0; nt < 4; nt++)
                    mma16816(acc[mt][nt], af[mt], bh[nt]);
        }
        __syncthreads();
    }

    #pragma unroll
    for (int mt = 0; mt < 4; mt++) {
        const int r0 = m0 + wm * 64 + mt * 16 + g;
        #pragma unroll
        for (int nt = 0; nt < 4; nt++) {
            const int n = n0 + wn * 32 + nt * 8 + 2 * tig;
            #pragma unroll
            for (int half = 0; half < 2; half++) {
                const int m = r0 + half * 8;
                float e = acc[mt][nt][half * 2 + 0];
                float o = acc[mt][nt][half * 2 + 1];
                if (MODE == 1) {
                    int t = m & (TT - 1);
                    int j0 = (n & (DD - 1)) >> 1;
                    float cc = cosT[(size_t)t * (DD / 2) + j0];
                    float ss = sinT[(size_t)t * (DD / 2) + j0];
                    float e2 = e * cc - o * ss;
                    o = e * ss + o * cc;
                    e = e2;
                }
                float2 vv = make_float2(e, o);
                if (MODE == 2) {
                    int b = m >> 11, t = m & (TT - 1);
                    int hk = n >> 7, d = n & (DD - 1);
                    *reinterpret_cast<float2*>(
                        &Cout[(((size_t)(b * HKK + hk) * TT + t) * DD) + d]) = vv;
                } else {
                    *reinterpret_cast<float2*>(&Cout[(size_t)m * N + n]) = vv;
                }
            }
        }
    }
}

// ---------------------------------------------------------------------------
// HMMA flash attention, bf16x3 both stages. Grid (T/128, H, B), 256 threads.
// Warp wm handles q-rows [wm*16, wm*16+16). kv tiles of 64.
// Smem (dyn, 141312B): Qh/Ql[128][136], Kh/Kl[64][136], VTh/VTl[128][72]
// ---------------------------------------------------------------------------
#define QS 136
#define VS 72
#define ATT_SMEM ((2*128*QS + 2*64*QS + 2*128*VS) * 2)

__global__ __launch_bounds__(256, 1)
void attn_mma(const float* __restrict__ q, const float* __restrict__ k,
              const float* __restrict__ v,
              __nv_bfloat16* __restrict__ yh, __nv_bfloat16* __restrict__ yl)
{
    extern __shared__ __nv_bfloat16 smp[];
    __nv_bfloat16* Qh  = smp;
    __nv_bfloat16* Ql  = Qh + 128 * QS;
    __nv_bfloat16* Kh  = Ql + 128 * QS;
    __nv_bfloat16* Kl  = Kh + 64 * QS;
    __nv_bfloat16* VTh = Kl + 64 * QS;
    __nv_bfloat16* VTl = VTh + 128 * VS;

    const int it = blockIdx.x;
    const int h  = blockIdx.y;
    const int b  = blockIdx.z;
    const int gk = h >> 2;
    const int t0 = it * 128;
    const int tid = threadIdx.x;
    const int wm = tid >> 5, lane = tid & 31;
    const int g = lane >> 2, tig = lane & 3;
    const float scale = 0.08838834764831845f;

    // Load Q tile (128 x 128) -> hi/lo smem
    for (int e = tid; e < 128 * 32; e += 256) {
        int row = e >> 5, c4 = (e & 31) << 2;
        float4 qv = *reinterpret_cast<const float4*>(
            &q[((size_t)(b * TT + t0 + row) * HH + h) * DD + c4]);
        uint32_t h0 = pack_hi2(qv.x, qv.y), h1 = pack_hi2(qv.z, qv.w);
        uint32_t l0 = pack_lo2(qv.x, qv.y, h0), l1 = pack_lo2(qv.z, qv.w, h1);
        *reinterpret_cast<uint2*>(&Qh[row * QS + c4]) = make_uint2(h0, h1);
        *reinterpret_cast<uint2*>(&Ql[row * QS + c4]) = make_uint2(l0, l1);
    }

    float o[16][4];
    #pragma unroll
    for (int dt = 0; dt < 16; dt++)
        #pragma unroll
        for (int e = 0; e < 4; e++) o[dt][e] = 0.f;
    float m0r = -INFINITY, m1r = -INFINITY, l0r = 0.f, l1r = 0.f;

    const int njt = 2 * it + 2;
    for (int jt = 0; jt < njt; jt++) {
        const int s0 = jt * 64;
        __syncthreads();   // prior mma reads done before tile overwrite

        // K tile (64 x 128) -> hi/lo
        for (int e = tid; e < 64 * 32; e += 256) {
            int row = e >> 5, c4 = (e & 31) << 2;
            float4 kv = *reinterpret_cast<const float4*>(
                &k[((size_t)(b * TT + s0 + row) * HKK + gk) * DD + c4]);
            uint32_t h0 = pack_hi2(kv.x, kv.y), h1 = pack_hi2(kv.z, kv.w);
            uint32_t l0 = pack_lo2(kv.x, kv.y, h0), l1 = pack_lo2(kv.z, kv.w, h1);
            *reinterpret_cast<uint2*>(&Kh[row * QS + c4]) = make_uint2(h0, h1);
            *reinterpret_cast<uint2*>(&Kl[row * QS + c4]) = make_uint2(l0, l1);
        }
        // V tile transposed: VT[d][s]; thread owns d = tid&127, s-block = tid>>7
        {
            const int d = tid & 127, sb = (tid >> 7) * 32;
            const float* vb = &v[((size_t)(b * TT + s0 + sb) * HKK + gk) * DD + d];
            #pragma unroll
            for (int i = 0; i < 8; i++) {
                float v0 = vb[(size_t)(i * 4 + 0) * HKK * DD];
                float v1 = vb[(size_t)(i * 4 + 1) * HKK * DD];
                float v2 = vb[(size_t)(i * 4 + 2) * HKK * DD];
                float v3 = vb[(size_t)(i * 4 + 3) * HKK * DD];
                uint32_t h0 = pack_hi2(v0, v1), h1 = pack_hi2(v2, v3);
                uint32_t l0 = pack_lo2(v0, v1, h0), l1 = pack_lo2(v2, v3, h1);
                int so = d * VS + sb + i * 4;
                *reinterpret_cast<uint2*>(&VTh[so]) = make_uint2(h0, h1);
                *reinterpret_cast<uint2*>(&VTl[so]) = make_uint2(l0, l1);
            }
        }
        __syncthreads();

        // S = Q K^T (warp: 16 x 64), bf16x3
        float sc[8][4];
        #pragma unroll
        for (int nt = 0; nt < 8; nt++)
            #pragma unroll
            for (int e = 0; e < 4; e++) sc[nt][e] = 0.f;

        #pragma unroll
        for (int kk = 0; kk < 8; kk++) {
            const int kcol = kk * 16 + 2 * tig;
            const int ar = (wm * 16 + g) * QS;
            uint32_t ah[4], al[4];
            ah[0] = *reinterpret_cast<const uint32_t*>(&Qh[ar + kcol]);
            ah[1] = *reinterpret_cast<const uint32_t*>(&Qh[ar + 8 * QS + kcol]);
            ah[2] = *reinterpret_cast<const uint32_t*>(&Qh[ar + kcol + 8]);
            ah[3] = *reinterpret_cast<const uint32_t*>(&Qh[ar + 8 * QS + kcol + 8]);
            al[0] = *reinterpret_cast<const uint32_t*>(&Ql[ar + kcol]);
            al[1] = *reinterpret_cast<const uint32_t*>(&Ql[ar + 8 * QS + kcol]);
            al[2] = *reinterpret_cast<const uint32_t*>(&Ql[ar + kcol + 8]);
            al[3] = *reinterpret_cast<const uint32_t*>(&Ql[ar + 8 * QS + kcol + 8]);
            #pragma unroll
            for (int nt = 0; nt < 8; nt++) {
                const int br = (nt * 8 + g) * QS;
                uint32_t bh[2], bl[2];
                bh[0] = *reinterpret_cast<const uint32_t*>(&Kh[br + kcol]);
                bh[1] = *reinterpret_cast<const uint32_t*>(&Kh[br + kcol + 8]);
                bl[0] = *reinterpret_cast<const uint32_t*>(&Kl[br + kcol]);
                bl[1] = *reinterpret_cast<const uint32_t*>(&Kl[br + kcol + 8]);
                mma16816(sc[nt], ah, bh);
                mma16816(sc[nt], ah, bl);
                mma16816(sc[nt], al, bh);
            }
        }

        // softmax (online)
        const int row0 = t0 + wm * 16 + g;
        const bool needmask = (s0 + 63 > row0);
        float mx0 = -INFINITY, mx1 = -INFINITY;
        #pragma unroll
        for (int nt = 0; nt < 8; nt++) {
            #pragma unroll
            for (int e = 0; e < 4; e++) sc[nt][e] *= scale;
            if (needmask) {
                int c0 = s0 + nt * 8 + 2 * tig;
                if (c0     > row0)     sc[nt][0] = -INFINITY;
                if (c0 + 1 > row0)     sc[nt][1] = -INFINITY;
                if (c0     > row0 + 8) sc[nt][2] = -INFINITY;
                if (c0 + 1 > row0 + 8) sc[nt][3] = -INFINITY;
            }
            mx0 = fmaxf(mx0, fmaxf(sc[nt][0], sc[nt][1]));
            mx1 = fmaxf(mx1, fmaxf(sc[nt][2], sc[nt][3]));
        }
        #pragma unroll
        for (int msk = 1; msk < 4; msk <<= 1) {
            mx0 = fmaxf(mx0, __shfl_xor_sync(0xffffffffu, mx0, msk));
            mx1 = fmaxf(mx1, __shfl_xor_sync(0xffffffffu, mx1, msk));
        }
        float mn0 = fmaxf(m0r, mx0), mn1 = fmaxf(m1r, mx1);
        float f0 = __expf(m0r - mn0), f1 = __expf(m1r - mn1);
        float s0s = 0.f, s1s = 0.f;
        #pragma unroll
        for (int nt = 0; nt < 8; nt++) {
            float p0 = __expf(sc[nt][0] - mn0); sc[nt][0] = p0; s0s += p0;
            float p1 = __expf(sc[nt][1] - mn0); sc[nt][1] = p1; s0s += p1;
            float p2 = __expf(sc[nt][2] - mn1); sc[nt][2] = p2; s1s += p2;
            float p3 = __expf(sc[nt][3] - mn1); sc[nt][3] = p3; s1s += p3;
        }
        #pragma unroll
        for (int msk = 1; msk < 4; msk <<= 1) {
            s0s += __shfl_xor_sync(0xffffffffu, s0s, msk);
            s1s += __shfl_xor_sync(0xffffffffu, s1s, msk);
        }
        l0r = l0r * f0 + s0s; l1r = l1r * f1 + s1s;
        m0r = mn0; m1r = mn1;
        #pragma unroll
        for (int dt = 0; dt < 16; dt++) {
            o[dt][0] *= f0; o[dt][1] *= f0;
            o[dt][2] *= f1; o[dt][3] *= f1;
        }

        // O += P V, bf16x3; P frags remapped in-register from sc
        #pragma unroll
        for (int kks = 0; kks < 4; kks++) {
            uint32_t pha[4], pla[4];
            pha[0] = pack_hi2(sc[2*kks][0],   sc[2*kks][1]);
            pla[0] = pack_lo2(sc[2*kks][0],   sc[2*kks][1],   pha[0]);
            pha[1] = pack_hi2(sc[2*kks][2],   sc[2*kks][3]);
            pla[1] = pack_lo2(sc[2*kks][2],   sc[2*kks][3],   pha[1]);
            pha[2] = pack_hi2(sc[2*kks+1][0], sc[2*kks+1][1]);
            pla[2] = pack_lo2(sc[2*kks+1][0], sc[2*kks+1][1], pha[2]);
            pha[3] = pack_hi2(sc[2*kks+1][2], sc[2*kks+1][3]);
            pla[3] = pack_lo2(sc[2*kks+1][2], sc[2*kks+1][3], pha[3]);
            #pragma unroll
            for (int dt = 0; dt < 16; dt++) {
                const int br = (dt * 8 + g) * VS + kks * 16 + 2 * tig;
                uint32_t bh[2], bl[2];
                bh[0] = *reinterpret_cast<const uint32_t*>(&VTh[br]);
                bh[1] = *reinterpret_cast<const uint32_t*>(&VTh[br + 8]);
                bl[0] = *reinterpret_cast<const uint32_t*>(&VTl[br]);
                bl[1] = *reinterpret_cast<const uint32_t*>(&VTl[br + 8]);
                mma16816(o[dt], pha, bh);
                mma16816(o[dt], pha, bl);
                mma16816(o[dt], pla, bh);
            }
        }
    }

    // Normalize and store hi/lo bf16
    const float inv0 = 1.f / l0r, inv1 = 1.f / l1r;
    const int row0 = t0 + wm * 16 + g;
    #pragma unroll
    for (int dt = 0; dt < 16; dt++) {
        int d = dt * 8 + 2 * tig;
        size_t b0 = ((size_t)(b * TT + row0) * HH + h) * DD + d;
        size_t b1 = ((size_t)(b * TT + row0 + 8) * HH + h) * DD + d;
        uint32_t h0 = pack_hi2(o[dt][0] * inv0, o[dt][1] * inv0);
        uint32_t l0 = pack_lo2(o[dt][0] * inv0, o[dt][1] * inv0, h0);
        uint32_t h1 = pack_hi2(o[dt][2] * inv1, o[dt][3] * inv1);
        uint32_t l1 = pack_lo2(o[dt][2] * inv1, o[dt][3] * inv1, h1);
        *reinterpret_cast<uint32_t*>(&yh[b0]) = h0;
        *reinterpret_cast<uint32_t*>(&yl[b0]) = l0;
        *reinterpret_cast<uint32_t*>(&yh[b1]) = h1;
        *reinterpret_cast<uint32_t*>(&yl[b1]) = l1;
    }
}

// ---------------------------------------------------------------------------
// Launch
// ---------------------------------------------------------------------------
extern "C" void kernel_launch(void* const* d_in, const int* in_sizes, int n_in,
                              void* d_out, int out_size)
{
    const float* x      = (const float*)d_in[0];
    const float* w_q    = (const float*)d_in[1];
    const float* w_k    = (const float*)d_in[2];
    const float* w_v    = (const float*)d_in[3];
    const float* w_proj = (const float*)d_in[4];
    const float* w_dk   = (const float*)d_in[5];
    const float* w_dv   = (const float*)d_in[6];
    const float* fcos   = (const float*)d_in[7];
    const float* fsin   = (const float*)d_in[8];

    float* out    = (float*)d_out;
    float* out_y  = out;
    float* out_kw = out + (size_t)BB * TT * CCH;
    float* out_vw = out_kw + (size_t)BB * HKK * TT * DD;

    static float *pq = nullptr, *pk = nullptr, *pv = nullptr;
    static __nv_bfloat16 *xh, *xl, *yh, *yl, *wh, *wl;
    if (!pq) {
        cudaGetSymbolAddress((void**)&pq, g_q);
        cudaGetSymbolAddress((void**)&pk, g_k);
        cudaGetSymbolAddress((void**)&pv, g_v);
        cudaGetSymbolAddress((void**)&xh, g_xh);
        cudaGetSymbolAddress((void**)&xl, g_xl);
        cudaGetSymbolAddress((void**)&yh, g_yh);
        cudaGetSymbolAddress((void**)&yl, g_yl);
        cudaGetSymbolAddress((void**)&wh, g_wh);
        cudaGetSymbolAddress((void**)&wl, g_wl);
        cudaFuncSetAttribute(attn_mma,
                             cudaFuncAttributeMaxDynamicSharedMemorySize, ATT_SMEM);
    }

    // 1) split x into bf16 hi/lo
    split_f32<<<(MR * CCH / 4 + 255) / 256, 256>>>(x, xh, xl, MR * CCH / 4);
    // 2) transpose + split weights
    dim3 tb(32, 8);
    transpose_w<<<dim3(CCH / 32, CCH / 32), tb>>>(w_q,    wh + WQ_OFF,  wl + WQ_OFF,  CCH, CCH);
    transpose_w<<<dim3(512 / 32, CCH / 32), tb>>>(w_k,    wh + WK_OFF,  wl + WK_OFF,  CCH, 512);
    transpose_w<<<dim3(512 / 32, CCH / 32), tb>>>(w_v,    wh + WV_OFF,  wl + WV_OFF,  CCH, 512);
    transpose_w<<<dim3(512 / 32, CCH / 32), tb>>>(w_dk,   wh + WDK_OFF, wl + WDK_OFF, CCH, 512);
    transpose_w<<<dim3(512 / 32, CCH / 32), tb>>>(w_dv,   wh + WDV_OFF, wl + WDV_OFF, CCH, 512);
    transpose_w<<<dim3(CCH / 32, CCH / 32), tb>>>(w_proj, wh + WP_OFF,  wl + WP_OFF,  CCH, CCH);

    dim3 blk(256);
    const int MT = MR / 128;
    // 3) projections (HMMA bf16x3)
    gemm_mma<1><<<dim3(16, MT), blk>>>(xh, xl, wh + WQ_OFF,  wl + WQ_OFF,  pq,     CCH, fcos, fsin);
    gemm_mma<1><<<dim3(4,  MT), blk>>>(xh, xl, wh + WK_OFF,  wl + WK_OFF,  pk,     512, fcos, fsin);
    gemm_mma<0><<<dim3(4,  MT), blk>>>(xh, xl, wh + WV_OFF,  wl + WV_OFF,  pv,     512, 0, 0);
    gemm_mma<2><<<dim3(4,  MT), blk>>>(xh, xl, wh + WDK_OFF, wl + WDK_OFF, out_kw, 512, 0, 0);
    gemm_mma<2><<<dim3(4,  MT), blk>>>(xh, xl, wh + WDV_OFF, wl + WDV_OFF, out_vw, 512, 0, 0);
    // 4) attention (HMMA bf16x3) -> y bf16 hi/lo
    attn_mma<<<dim3(TT / 128, HH, BB), blk, ATT_SMEM>>>(pq, pk, pv, yh, yl);
    // 5) output projection
    gemm_mma<0><<<dim3(16, MT), blk>>>(yh, yl, wh + WP_OFF, wl + WP_OFF, out_y, CCH, 0, 0);
}

// round 10
// speedup vs baseline: 3.0364x; 1.1494x over previous
#include <cuda_runtime.h>
#include <cuda_bf16.h>
#include <math.h>
#include <stdint.h>

// Problem constants
#define BB   2
#define TT   2048
#define CCH  2048
#define HH   16
#define HKK  4
#define DD   128
#define MR   (BB*TT)          // 4096 rows
#define KGEMM 2048            // K of every GEMM here

// Weight scratch offsets (bf16 transposed [N][K]); k,v,dk,dv contiguous
#define WQ_OFF  0u
#define WK_OFF  4194304u
#define WP_OFF  8388608u
#define WTOT    12582912u

// ---------------------------------------------------------------------------
// Scratch (device globals; no allocation allowed)
// ---------------------------------------------------------------------------
__device__ float g_q[(size_t)BB*TT*HH*DD];      // (B,T,H*D) after RoPE (fp32)
__device__ float g_k[(size_t)BB*TT*HKK*DD];     // (B,T,HK*D) after RoPE
__device__ float g_v[(size_t)BB*TT*HKK*DD];     // (B,T,HK*D)
__device__ __nv_bfloat16 g_xh[(size_t)MR*CCH], g_xl[(size_t)MR*CCH];
__device__ __nv_bfloat16 g_yh[(size_t)MR*CCH], g_yl[(size_t)MR*CCH];
__device__ __nv_bfloat16 g_wh[WTOT], g_wl[WTOT];

// ---------------------------------------------------------------------------
// mma.sync m16n8k16 bf16 + helpers
// ---------------------------------------------------------------------------
__device__ __forceinline__ void mma16816(float* c, const uint32_t* a, const uint32_t* b)
{
    asm volatile(
        "mma.sync.aligned.m16n8k16.row.col.f32.bf16.bf16.f32 "
        "{%0,%1,%2,%3}, {%4,%5,%6,%7}, {%8,%9}, {%0,%1,%2,%3};\n"
        : "+f"(c[0]), "+f"(c[1]), "+f"(c[2]), "+f"(c[3])
        : "r"(a[0]), "r"(a[1]), "r"(a[2]), "r"(a[3]), "r"(b[0]), "r"(b[1]));
}

__device__ __forceinline__ uint32_t pack_hi2(float a, float b)
{
    __nv_bfloat162 h = __floats2bfloat162_rn(a, b);
    return *reinterpret_cast<uint32_t*>(&h);
}
__device__ __forceinline__ uint32_t pack_lo2(float a, float b, uint32_t hi)
{
    __nv_bfloat162 h = *reinterpret_cast<__nv_bfloat162*>(&hi);
    __nv_bfloat162 l = __floats2bfloat162_rn(a - __bfloat162float(h.x),
                                             b - __bfloat162float(h.y));
    return *reinterpret_cast<uint32_t*>(&l);
}
__device__ __forceinline__ uint32_t smem_u32(const void* p)
{
    uint32_t a;
    asm("{ .reg .u64 t; cvta.to.shared.u64 t, %1; cvt.u32.u64 %0, t; }"
        : "=r"(a) : "l"(p));
    return a;
}
__device__ __forceinline__ void cpa16(uint32_t s, const void* g)
{
    asm volatile("cp.async.cg.shared.global [%0], [%1], 16;" :: "r"(s), "l"(g));
}
#define CP_COMMIT asm volatile("cp.async.commit_group;" ::: "memory")
#define CP_WAIT1  asm volatile("cp.async.wait_group 1;" ::: "memory")
#define CP_WAIT0  asm volatile("cp.async.wait_group 0;" ::: "memory")

// ---------------------------------------------------------------------------
// Split fp32 -> bf16 hi/lo (elementwise, vectorized)
// ---------------------------------------------------------------------------
__global__ __launch_bounds__(256)
void split_f32(const float* __restrict__ s, __nv_bfloat16* __restrict__ dh,
               __nv_bfloat16* __restrict__ dl, int n4)
{
    int i = blockIdx.x * blockDim.x + threadIdx.x;
    if (i >= n4) return;
    float4 v = reinterpret_cast<const float4*>(s)[i];
    uint32_t h0 = pack_hi2(v.x, v.y), h1 = pack_hi2(v.z, v.w);
    uint32_t l0 = pack_lo2(v.x, v.y, h0), l1 = pack_lo2(v.z, v.w, h1);
    reinterpret_cast<uint2*>(dh)[i] = make_uint2(h0, h1);
    reinterpret_cast<uint2*>(dl)[i] = make_uint2(l0, l1);
}

// ---------------------------------------------------------------------------
// Transpose W[K][N] fp32 -> Wt[N][K] bf16 hi/lo. Block (32,8), grid (N/32,K/32).
// ---------------------------------------------------------------------------
__global__ __launch_bounds__(256)
void transpose_w(const float* __restrict__ W, __nv_bfloat16* __restrict__ Th,
                 __nv_bfloat16* __restrict__ Tl, int K, int N)
{
    __shared__ float tile[32][33];
    const int n0 = blockIdx.x * 32, k0 = blockIdx.y * 32;
    const int tx = threadIdx.x, ty = threadIdx.y;
    #pragma unroll
    for (int i = 0; i < 4; i++)
        tile[ty + i * 8][tx] = W[(size_t)(k0 + ty + i * 8) * N + n0 + tx];
    __syncthreads();
    #pragma unroll
    for (int i = 0; i < 4; i++) {
        int n = ty + i * 8;
        float v = tile[tx][n];
        __nv_bfloat16 h = __float2bfloat16(v);
        __nv_bfloat16 l = __float2bfloat16(v - __bfloat162float(h));
        size_t off = (size_t)(n0 + n) * K + k0 + tx;
        Th[off] = h;
        Tl[off] = l;
    }
}

// ---------------------------------------------------------------------------
// HMMA GEMM, 2-stage cp.async pipeline. C[4096,N] = A * W, bf16x3 split.
// CTA: 128x128 tile, 8 warps (2m x 4n), BK=32, dynamic smem 2 x 40960 B.
// MODE 0: plain fp32 -> C0 (width N). MODE 1: RoPE -> C0 (width N).
// MODE 3: fused kvdd (N=2048): sub = n0>>9 selects
//   0: RoPE -> C0[m][512], 1: plain -> C1[m][512],
//   2/3: (B,HK,T,D) transposed -> C2 / C3.
// ---------------------------------------------------------------------------
#define SA 40
#define GSTG 40960
#define GEMM_DYN (2 * GSTG)

template<int MODE>
__global__ __launch_bounds__(256, 2)
void gemm_mma(const __nv_bfloat16* __restrict__ AH, const __nv_bfloat16* __restrict__ AL,
              const __nv_bfloat16* __restrict__ BH, const __nv_bfloat16* __restrict__ BL,
              float* __restrict__ C0, float* __restrict__ C1,
              float* __restrict__ C2, float* __restrict__ C3, int N,
              const float* __restrict__ cosT, const float* __restrict__ sinT)
{
    extern __shared__ char gsm[];
    const uint32_t sb = smem_u32(gsm);
    const int tid = threadIdx.x;
    const int wid = tid >> 5, lane = tid & 31;
    const int g = lane >> 2, tig = lane & 3;
    const int wm = wid >> 2, wn = wid & 3;
    const int m0 = blockIdx.y * 128;
    const int n0 = blockIdx.x * 128;

    float acc[4][4][4];
    #pragma unroll
    for (int mt = 0; mt < 4; mt++)
        #pragma unroll
        for (int nt = 0; nt < 4; nt++)
            #pragma unroll
            for (int e = 0; e < 4; e++) acc[mt][nt][e] = 0.f;

    const int row = tid >> 2, part = tid & 3;
    const uint32_t so = (uint32_t)(row * SA + part * 8) * 2;

    // async load of one 32-K chunk into given stage
    auto issue_load = [&](int stage, int kc) {
        const int k0 = kc * 32;
        const uint32_t st = sb + stage * GSTG;
        #pragma unroll
        for (int it = 0; it < 2; it++) {
            int r2 = row + it * 64;
            size_t ga = (size_t)(m0 + r2) * KGEMM + k0 + part * 8;
            size_t gb = (size_t)(n0 + r2) * KGEMM + k0 + part * 8;
            uint32_t s2 = so + (uint32_t)(it * 64 * SA * 2);
            cpa16(st + s2,         AH + ga);
            cpa16(st + 10240 + s2, AL + ga);
            cpa16(st + 20480 + s2, BH + gb);
            cpa16(st + 30720 + s2, BL + gb);
        }
        CP_COMMIT;
    };

    const int nk = KGEMM / 32;   // 64
    issue_load(0, 0);

    for (int kc = 0; kc < nk; kc++) {
        const int st = kc & 1;
        if (kc + 1 < nk) { issue_load((kc + 1) & 1, kc + 1); CP_WAIT1; }
        else             { CP_WAIT0; }
        __syncthreads();

        const __nv_bfloat16* sAH = reinterpret_cast<const __nv_bfloat16*>(gsm + st * GSTG);
        const __nv_bfloat16* sAL = reinterpret_cast<const __nv_bfloat16*>(gsm + st * GSTG + 10240);
        const __nv_bfloat16* sBH = reinterpret_cast<const __nv_bfloat16*>(gsm + st * GSTG + 20480);
        const __nv_bfloat16* sBL = reinterpret_cast<const __nv_bfloat16*>(gsm + st * GSTG + 30720);

        #pragma unroll
        for (int ks = 0; ks < 2; ks++) {
            const int kcol = ks * 16 + 2 * tig;
            uint32_t bh[4][2], bl[4][2];
            #pragma unroll
            for (int nt = 0; nt < 4; nt++) {
                int brow = (wn * 32 + nt * 8 + g) * SA;
                bh[nt][0] = *reinterpret_cast<const uint32_t*>(&sBH[brow + kcol]);
                bh[nt][1] = *reinterpret_cast<const uint32_t*>(&sBH[brow + kcol + 8]);
                bl[nt][0] = *reinterpret_cast<const uint32_t*>(&sBL[brow + kcol]);
                bl[nt][1] = *reinterpret_cast<const uint32_t*>(&sBL[brow + kcol + 8]);
            }
            uint32_t af[4][4];
            #pragma unroll
            for (int mt = 0; mt < 4; mt++) {
                int ar = (wm * 64 + mt * 16 + g) * SA;
                af[mt][0] = *reinterpret_cast<const uint32_t*>(&sAH[ar + kcol]);
                af[mt][1] = *reinterpret_cast<const uint32_t*>(&sAH[ar + 8 * SA + kcol]);
                af[mt][2] = *reinterpret_cast<const uint32_t*>(&sAH[ar + kcol + 8]);
                af[mt][3] = *reinterpret_cast<const uint32_t*>(&sAH[ar + 8 * SA + kcol + 8]);
            }
            #pragma unroll
            for (int mt = 0; mt < 4; mt++)
                #pragma unroll
                for (int nt = 0; nt < 4; nt++) {
                    mma16816(acc[mt][nt], af[mt], bh[nt]);
                    mma16816(acc[mt][nt], af[mt], bl[nt]);
                }
            #pragma unroll
            for (int mt = 0; mt < 4; mt++) {
                int ar = (wm * 64 + mt * 16 + g) * SA;
                af[mt][0] = *reinterpret_cast<const uint32_t*>(&sAL[ar + kcol]);
                af[mt][1] = *reinterpret_cast<const uint32_t*>(&sAL[ar + 8 * SA + kcol]);
                af[mt][2] = *reinterpret_cast<const uint32_t*>(&sAL[ar + kcol + 8]);
                af[mt][3] = *reinterpret_cast<const uint32_t*>(&sAL[ar + 8 * SA + kcol + 8]);
            }
            #pragma unroll
            for (int mt = 0; mt < 4; mt++)
                #pragma unroll
                for (int nt = 0; nt < 4; nt++)
                    mma16816(acc[mt][nt], af[mt], bh[nt]);
        }
        __syncthreads();
    }

    // Epilogue
    const int sub = n0 >> 9;   // uniform per CTA (used by MODE 3)
    #pragma unroll
    for (int mt = 0; mt < 4; mt++) {
        const int r0 = m0 + wm * 64 + mt * 16 + g;
        #pragma unroll
        for (int nt = 0; nt < 4; nt++) {
            const int n = n0 + wn * 32 + nt * 8 + 2 * tig;
            #pragma unroll
            for (int half = 0; half < 2; half++) {
                const int m = r0 + half * 8;
                float e = acc[mt][nt][half * 2 + 0];
                float o = acc[mt][nt][half * 2 + 1];
                const bool dorope = (MODE == 1) || (MODE == 3 && sub == 0);
                if (dorope) {
                    int t = m & (TT - 1);
                    int j0 = (n & (DD - 1)) >> 1;
                    float cc = cosT[(size_t)t * (DD / 2) + j0];
                    float ss = sinT[(size_t)t * (DD / 2) + j0];
                    float e2 = e * cc - o * ss;
                    o = e * ss + o * cc;
                    e = e2;
                }
                float2 vv = make_float2(e, o);
                if (MODE == 3) {
                    int nn = n & 511;
                    if (sub == 0) {
                        *reinterpret_cast<float2*>(&C0[(size_t)m * 512 + nn]) = vv;
                    } else if (sub == 1) {
                        *reinterpret_cast<float2*>(&C1[(size_t)m * 512 + nn]) = vv;
                    } else {
                        int b = m >> 11, t = m & (TT - 1);
                        int hk = nn >> 7, d = n & (DD - 1);
                        float* dst = (sub == 2) ? C2 : C3;
                        *reinterpret_cast<float2*>(
                            &dst[(((size_t)(b * HKK + hk) * TT + t) * DD) + d]) = vv;
                    }
                } else {
                    *reinterpret_cast<float2*>(&C0[(size_t)m * N + n]) = vv;
                }
            }
        }
    }
}

// ---------------------------------------------------------------------------
// HMMA flash attention, bf16x3 both stages (unchanged from R9; known good).
// ---------------------------------------------------------------------------
#define QS 136
#define VS 72
#define ATT_SMEM ((2*128*QS + 2*64*QS + 2*128*VS) * 2)

__global__ __launch_bounds__(256, 1)
void attn_mma(const float* __restrict__ q, const float* __restrict__ k,
              const float* __restrict__ v,
              __nv_bfloat16* __restrict__ yh, __nv_bfloat16* __restrict__ yl)
{
    extern __shared__ __nv_bfloat16 smp[];
    __nv_bfloat16* Qh  = smp;
    __nv_bfloat16* Ql  = Qh + 128 * QS;
    __nv_bfloat16* Kh  = Ql + 128 * QS;
    __nv_bfloat16* Kl  = Kh + 64 * QS;
    __nv_bfloat16* VTh = Kl + 64 * QS;
    __nv_bfloat16* VTl = VTh + 128 * VS;

    const int it = blockIdx.x;
    const int h  = blockIdx.y;
    const int b  = blockIdx.z;
    const int gk = h >> 2;
    const int t0 = it * 128;
    const int tid = threadIdx.x;
    const int wm = tid >> 5, lane = tid & 31;
    const int g = lane >> 2, tig = lane & 3;
    const float scale = 0.08838834764831845f;

    for (int e = tid; e < 128 * 32; e += 256) {
        int row = e >> 5, c4 = (e & 31) << 2;
        float4 qv = *reinterpret_cast<const float4*>(
            &q[((size_t)(b * TT + t0 + row) * HH + h) * DD + c4]);
        uint32_t h0 = pack_hi2(qv.x, qv.y), h1 = pack_hi2(qv.z, qv.w);
        uint32_t l0 = pack_lo2(qv.x, qv.y, h0), l1 = pack_lo2(qv.z, qv.w, h1);
        *reinterpret_cast<uint2*>(&Qh[row * QS + c4]) = make_uint2(h0, h1);
        *reinterpret_cast<uint2*>(&Ql[row * QS + c4]) = make_uint2(l0, l1);
    }

    float o[16][4];
    #pragma unroll
    for (int dt = 0; dt < 16; dt++)
        #pragma unroll
        for (int e = 0; e < 4; e++) o[dt][e] = 0.f;
    float m0r = -INFINITY, m1r = -INFINITY, l0r = 0.f, l1r = 0.f;

    const int njt = 2 * it + 2;
    for (int jt = 0; jt < njt; jt++) {
        const int s0 = jt * 64;
        __syncthreads();

        for (int e = tid; e < 64 * 32; e += 256) {
            int row = e >> 5, c4 = (e & 31) << 2;
            float4 kv = *reinterpret_cast<const float4*>(
                &k[((size_t)(b * TT + s0 + row) * HKK + gk) * DD + c4]);
            uint32_t h0 = pack_hi2(kv.x, kv.y), h1 = pack_hi2(kv.z, kv.w);
            uint32_t l0 = pack_lo2(kv.x, kv.y, h0), l1 = pack_lo2(kv.z, kv.w, h1);
            *reinterpret_cast<uint2*>(&Kh[row * QS + c4]) = make_uint2(h0, h1);
            *reinterpret_cast<uint2*>(&Kl[row * QS + c4]) = make_uint2(l0, l1);
        }
        {
            const int d = tid & 127, sb2 = (tid >> 7) * 32;
            const float* vb = &v[((size_t)(b * TT + s0 + sb2) * HKK + gk) * DD + d];
            #pragma unroll
            for (int i = 0; i < 8; i++) {
                float v0 = vb[(size_t)(i * 4 + 0) * HKK * DD];
                float v1 = vb[(size_t)(i * 4 + 1) * HKK * DD];
                float v2 = vb[(size_t)(i * 4 + 2) * HKK * DD];
                float v3 = vb[(size_t)(i * 4 + 3) * HKK * DD];
                uint32_t h0 = pack_hi2(v0, v1), h1 = pack_hi2(v2, v3);
                uint32_t l0 = pack_lo2(v0, v1, h0), l1 = pack_lo2(v2, v3, h1);
                int so = d * VS + sb2 + i * 4;
                *reinterpret_cast<uint2*>(&VTh[so]) = make_uint2(h0, h1);
                *reinterpret_cast<uint2*>(&VTl[so]) = make_uint2(l0, l1);
            }
        }
        __syncthreads();

        float sc[8][4];
        #pragma unroll
        for (int nt = 0; nt < 8; nt++)
            #pragma unroll
            for (int e = 0; e < 4; e++) sc[nt][e] = 0.f;

        #pragma unroll
        for (int kk = 0; kk < 8; kk++) {
            const int kcol = kk * 16 + 2 * tig;
            const int ar = (wm * 16 + g) * QS;
            uint32_t ah[4], al[4];
            ah[0] = *reinterpret_cast<const uint32_t*>(&Qh[ar + kcol]);
            ah[1] = *reinterpret_cast<const uint32_t*>(&Qh[ar + 8 * QS + kcol]);
            ah[2] = *reinterpret_cast<const uint32_t*>(&Qh[ar + kcol + 8]);
            ah[3] = *reinterpret_cast<const uint32_t*>(&Qh[ar + 8 * QS + kcol + 8]);
            al[0] = *reinterpret_cast<const uint32_t*>(&Ql[ar + kcol]);
            al[1] = *reinterpret_cast<const uint32_t*>(&Ql[ar + 8 * QS + kcol]);
            al[2] = *reinterpret_cast<const uint32_t*>(&Ql[ar + kcol + 8]);
            al[3] = *reinterpret_cast<const uint32_t*>(&Ql[ar + 8 * QS + kcol + 8]);
            #pragma unroll
            for (int nt = 0; nt < 8; nt++) {
                const int br = (nt * 8 + g) * QS;
                uint32_t bh[2], bl[2];
                bh[0] = *reinterpret_cast<const uint32_t*>(&Kh[br + kcol]);
                bh[1] = *reinterpret_cast<const uint32_t*>(&Kh[br + kcol + 8]);
                bl[0] = *reinterpret_cast<const uint32_t*>(&Kl[br + kcol]);
                bl[1] = *reinterpret_cast<const uint32_t*>(&Kl[br + kcol + 8]);
                mma16816(sc[nt], ah, bh);
                mma16816(sc[nt], ah, bl);
                mma16816(sc[nt], al, bh);
            }
        }

        const int row0 = t0 + wm * 16 + g;
        const bool needmask = (s0 + 63 > row0);
        float mx0 = -INFINITY, mx1 = -INFINITY;
        #pragma unroll
        for (int nt = 0; nt < 8; nt++) {
            #pragma unroll
            for (int e = 0; e < 4; e++) sc[nt][e] *= scale;
            if (needmask) {
                int c0 = s0 + nt * 8 + 2 * tig;
                if (c0     > row0)     sc[nt][0] = -INFINITY;
                if (c0 + 1 > row0)     sc[nt][1] = -INFINITY;
                if (c0     > row0 + 8) sc[nt][2] = -INFINITY;
                if (c0 + 1 > row0 + 8) sc[nt][3] = -INFINITY;
            }
            mx0 = fmaxf(mx0, fmaxf(sc[nt][0], sc[nt][1]));
            mx1 = fmaxf(mx1, fmaxf(sc[nt][2], sc[nt][3]));
        }
        #pragma unroll
        for (int msk = 1; msk < 4; msk <<= 1) {
            mx0 = fmaxf(mx0, __shfl_xor_sync(0xffffffffu, mx0, msk));
            mx1 = fmaxf(mx1, __shfl_xor_sync(0xffffffffu, mx1, msk));
        }
        float mn0 = fmaxf(m0r, mx0), mn1 = fmaxf(m1r, mx1);
        float f0 = __expf(m0r - mn0), f1 = __expf(m1r - mn1);
        float s0s = 0.f, s1s = 0.f;
        #pragma unroll
        for (int nt = 0; nt < 8; nt++) {
            float p0 = __expf(sc[nt][0] - mn0); sc[nt][0] = p0; s0s += p0;
            float p1 = __expf(sc[nt][1] - mn0); sc[nt][1] = p1; s0s += p1;
            float p2 = __expf(sc[nt][2] - mn1); sc[nt][2] = p2; s1s += p2;
            float p3 = __expf(sc[nt][3] - mn1); sc[nt][3] = p3; s1s += p3;
        }
        #pragma unroll
        for (int msk = 1; msk < 4; msk <<= 1) {
            s0s += __shfl_xor_sync(0xffffffffu, s0s, msk);
            s1s += __shfl_xor_sync(0xffffffffu, s1s, msk);
        }
        l0r = l0r * f0 + s0s; l1r = l1r * f1 + s1s;
        m0r = mn0; m1r = mn1;
        #pragma unroll
        for (int dt = 0; dt < 16; dt++) {
            o[dt][0] *= f0; o[dt][1] *= f0;
            o[dt][2] *= f1; o[dt][3] *= f1;
        }

        #pragma unroll
        for (int kks = 0; kks < 4; kks++) {
            uint32_t pha[4], pla[4];
            pha[0] = pack_hi2(sc[2*kks][0],   sc[2*kks][1]);
            pla[0] = pack_lo2(sc[2*kks][0],   sc[2*kks][1],   pha[0]);
            pha[1] = pack_hi2(sc[2*kks][2],   sc[2*kks][3]);
            pla[1] = pack_lo2(sc[2*kks][2],   sc[2*kks][3],   pha[1]);
            pha[2] = pack_hi2(sc[2*kks+1][0], sc[2*kks+1][1]);
            pla[2] = pack_lo2(sc[2*kks+1][0], sc[2*kks+1][1], pha[2]);
            pha[3] = pack_hi2(sc[2*kks+1][2], sc[2*kks+1][3]);
            pla[3] = pack_lo2(sc[2*kks+1][2], sc[2*kks+1][3], pha[3]);
            #pragma unroll
            for (int dt = 0; dt < 16; dt++) {
                const int br = (dt * 8 + g) * VS + kks * 16 + 2 * tig;
                uint32_t bh[2], bl[2];
                bh[0] = *reinterpret_cast<const uint32_t*>(&VTh[br]);
                bh[1] = *reinterpret_cast<const uint32_t*>(&VTh[br + 8]);
                bl[0] = *reinterpret_cast<const uint32_t*>(&VTl[br]);
                bl[1] = *reinterpret_cast<const uint32_t*>(&VTl[br + 8]);
                mma16816(o[dt], pha, bh);
                mma16816(o[dt], pha, bl);
                mma16816(o[dt], pla, bh);
            }
        }
    }

    const float inv0 = 1.f / l0r, inv1 = 1.f / l1r;
    const int row0 = t0 + wm * 16 + g;
    #pragma unroll
    for (int dt = 0; dt < 16; dt++) {
        int d = dt * 8 + 2 * tig;
        size_t b0 = ((size_t)(b * TT + row0) * HH + h) * DD + d;
        size_t b1 = ((size_t)(b * TT + row0 + 8) * HH + h) * DD + d;
        uint32_t h0 = pack_hi2(o[dt][0] * inv0, o[dt][1] * inv0);
        uint32_t l0 = pack_lo2(o[dt][0] * inv0, o[dt][1] * inv0, h0);
        uint32_t h1 = pack_hi2(o[dt][2] * inv1, o[dt][3] * inv1);
        uint32_t l1 = pack_lo2(o[dt][2] * inv1, o[dt][3] * inv1, h1);
        *reinterpret_cast<uint32_t*>(&yh[b0]) = h0;
        *reinterpret_cast<uint32_t*>(&yl[b0]) = l0;
        *reinterpret_cast<uint32_t*>(&yh[b1]) = h1;
        *reinterpret_cast<uint32_t*>(&yl[b1]) = l1;
    }
}

// ---------------------------------------------------------------------------
// Launch
// ---------------------------------------------------------------------------
extern "C" void kernel_launch(void* const* d_in, const int* in_sizes, int n_in,
                              void* d_out, int out_size)
{
    const float* x      = (const float*)d_in[0];
    const float* w_q    = (const float*)d_in[1];
    const float* w_k    = (const float*)d_in[2];
    const float* w_v    = (const float*)d_in[3];
    const float* w_proj = (const float*)d_in[4];
    const float* w_dk   = (const float*)d_in[5];
    const float* w_dv   = (const float*)d_in[6];
    const float* fcos   = (const float*)d_in[7];
    const float* fsin   = (const float*)d_in[8];

    float* out    = (float*)d_out;
    float* out_y  = out;
    float* out_kw = out + (size_t)BB * TT * CCH;
    float* out_vw = out_kw + (size_t)BB * HKK * TT * DD;

    static float *pq = nullptr, *pk = nullptr, *pv = nullptr;
    static __nv_bfloat16 *xh, *xl, *yh, *yl, *wh, *wl;
    if (!pq) {
        cudaGetSymbolAddress((void**)&pq, g_q);
        cudaGetSymbolAddress((void**)&pk, g_k);
        cudaGetSymbolAddress((void**)&pv, g_v);
        cudaGetSymbolAddress((void**)&xh, g_xh);
        cudaGetSymbolAddress((void**)&xl, g_xl);
        cudaGetSymbolAddress((void**)&yh, g_yh);
        cudaGetSymbolAddress((void**)&yl, g_yl);
        cudaGetSymbolAddress((void**)&wh, g_wh);
        cudaGetSymbolAddress((void**)&wl, g_wl);
        cudaFuncSetAttribute(attn_mma,
                             cudaFuncAttributeMaxDynamicSharedMemorySize, ATT_SMEM);
        cudaFuncSetAttribute(gemm_mma<0>,
                             cudaFuncAttributeMaxDynamicSharedMemorySize, GEMM_DYN);
        cudaFuncSetAttribute(gemm_mma<1>,
                             cudaFuncAttributeMaxDynamicSharedMemorySize, GEMM_DYN);
        cudaFuncSetAttribute(gemm_mma<3>,
                             cudaFuncAttributeMaxDynamicSharedMemorySize, GEMM_DYN);
    }

    // 1) split x into bf16 hi/lo
    split_f32<<<(MR * CCH / 4 + 255) / 256, 256>>>(x, xh, xl, MR * CCH / 4);
    // 2) transpose + split weights (k,v,dk,dv contiguous at WK_OFF)
    dim3 tb(32, 8);
    transpose_w<<<dim3(CCH / 32, CCH / 32), tb>>>(w_q,    wh + WQ_OFF,            wl + WQ_OFF,            CCH, CCH);
    transpose_w<<<dim3(512 / 32, CCH / 32), tb>>>(w_k,    wh + WK_OFF,            wl + WK_OFF,            CCH, 512);
    transpose_w<<<dim3(512 / 32, CCH / 32), tb>>>(w_v,    wh + WK_OFF + 1048576,  wl + WK_OFF + 1048576,  CCH, 512);
    transpose_w<<<dim3(512 / 32, CCH / 32), tb>>>(w_dk,   wh + WK_OFF + 2097152,  wl + WK_OFF + 2097152,  CCH, 512);
    transpose_w<<<dim3(512 / 32, CCH / 32), tb>>>(w_dv,   wh + WK_OFF + 3145728,  wl + WK_OFF + 3145728,  CCH, 512);
    transpose_w<<<dim3(CCH / 32, CCH / 32), tb>>>(w_proj, wh + WP_OFF,            wl + WP_OFF,            CCH, CCH);

    dim3 blk(256);
    const int MT = MR / 128;
    // 3) q projection + fused k/v/dk/dv projection (HMMA bf16x3, cp.async)
    gemm_mma<1><<<dim3(16, MT), blk, GEMM_DYN>>>(xh, xl, wh + WQ_OFF, wl + WQ_OFF,
                                                 pq, 0, 0, 0, CCH, fcos, fsin);
    gemm_mma<3><<<dim3(16, MT), blk, GEMM_DYN>>>(xh, xl, wh + WK_OFF, wl + WK_OFF,
                                                 pk, pv, out_kw, out_vw, 2048, fcos, fsin);
    // 4) attention (HMMA bf16x3) -> y bf16 hi/lo
    attn_mma<<<dim3(TT / 128, HH, BB), blk, ATT_SMEM>>>(pq, pk, pv, yh, yl);
    // 5) output projection
    gemm_mma<0><<<dim3(16, MT), blk, GEMM_DYN>>>(yh, yl, wh + WP_OFF, wl + WP_OFF,
                                                 out_y, 0, 0, 0, CCH, 0, 0);
}

// round 12
// speedup vs baseline: 3.2051x; 1.0556x over previous
#include <cuda_runtime.h>
#include <cuda_bf16.h>
#include <math.h>
#include <stdint.h>

// Problem constants
#define BB   2
#define TT   2048
#define CCH  2048
#define HH   16
#define HKK  4
#define DD   128
#define MR   (BB*TT)          // 4096 rows
#define KGEMM 2048            // K of every GEMM here

// Weight scratch offsets (bf16 transposed [N][K]); k,v,dk,dv contiguous
#define WQ_OFF  0u
#define WK_OFF  4194304u
#define WP_OFF  8388608u
#define WTOT    12582912u

// ---------------------------------------------------------------------------
// Scratch (device globals; no allocation allowed)
// ---------------------------------------------------------------------------
__device__ float g_q[(size_t)BB*TT*HH*DD];      // (B,T,H*D) after RoPE (fp32)
__device__ float g_k[(size_t)BB*TT*HKK*DD];     // (B,T,HK*D) after RoPE
__device__ float g_v[(size_t)BB*TT*HKK*DD];     // (B,T,HK*D)
__device__ __nv_bfloat16 g_xh[(size_t)MR*CCH], g_xl[(size_t)MR*CCH];
__device__ __nv_bfloat16 g_yh[(size_t)MR*CCH], g_yl[(size_t)MR*CCH];
__device__ __nv_bfloat16 g_wh[WTOT], g_wl[WTOT];

// ---------------------------------------------------------------------------
// mma.sync m16n8k16 bf16 + helpers
// ---------------------------------------------------------------------------
__device__ __forceinline__ void mma16816(float* c, const uint32_t* a, const uint32_t* b)
{
    asm volatile(
        "mma.sync.aligned.m16n8k16.row.col.f32.bf16.bf16.f32 "
        "{%0,%1,%2,%3}, {%4,%5,%6,%7}, {%8,%9}, {%0,%1,%2,%3};\n"
        : "+f"(c[0]), "+f"(c[1]), "+f"(c[2]), "+f"(c[3])
        : "r"(a[0]), "r"(a[1]), "r"(a[2]), "r"(a[3]), "r"(b[0]), "r"(b[1]));
}

__device__ __forceinline__ void ldsm4(uint32_t* d, uint32_t addr)
{
    asm volatile("ldmatrix.sync.aligned.m8n8.x4.shared.b16 {%0,%1,%2,%3}, [%4];"
        : "=r"(d[0]), "=r"(d[1]), "=r"(d[2]), "=r"(d[3]) : "r"(addr));
}

__device__ __forceinline__ uint32_t pack_hi2(float a, float b)
{
    __nv_bfloat162 h = __floats2bfloat162_rn(a, b);
    return *reinterpret_cast<uint32_t*>(&h);
}
__device__ __forceinline__ uint32_t pack_lo2(float a, float b, uint32_t hi)
{
    __nv_bfloat162 h = *reinterpret_cast<__nv_bfloat162*>(&hi);
    __nv_bfloat162 l = __floats2bfloat162_rn(a - __bfloat162float(h.x),
                                             b - __bfloat162float(h.y));
    return *reinterpret_cast<uint32_t*>(&l);
}
__device__ __forceinline__ uint32_t smem_u32(const void* p)
{
    uint32_t a;
    asm("{ .reg .u64 t; cvta.to.shared.u64 t, %1; cvt.u32.u64 %0, t; }"
        : "=r"(a) : "l"(p));
    return a;
}
__device__ __forceinline__ void cpa16(uint32_t s, const void* g)
{
    asm volatile("cp.async.cg.shared.global [%0], [%1], 16;" :: "r"(s), "l"(g));
}
#define CP_COMMIT asm volatile("cp.async.commit_group;" ::: "memory")
#define CP_WAIT1  asm volatile("cp.async.wait_group 1;" ::: "memory")
#define CP_WAIT0  asm volatile("cp.async.wait_group 0;" ::: "memory")

// ---------------------------------------------------------------------------
// Split fp32 -> bf16 hi/lo (elementwise, vectorized)
// ---------------------------------------------------------------------------
__global__ __launch_bounds__(256)
void split_f32(const float* __restrict__ s, __nv_bfloat16* __restrict__ dh,
               __nv_bfloat16* __restrict__ dl, int n4)
{
    int i = blockIdx.x * blockDim.x + threadIdx.x;
    if (i >= n4) return;
    float4 v = reinterpret_cast<const float4*>(s)[i];
    uint32_t h0 = pack_hi2(v.x, v.y), h1 = pack_hi2(v.z, v.w);
    uint32_t l0 = pack_lo2(v.x, v.y, h0), l1 = pack_lo2(v.z, v.w, h1);
    reinterpret_cast<uint2*>(dh)[i] = make_uint2(h0, h1);
    reinterpret_cast<uint2*>(dl)[i] = make_uint2(l0, l1);
}

// ---------------------------------------------------------------------------
// Transpose W[K][N] fp32 -> Wt[N][K] bf16 hi/lo. Block (32,8), grid (N/32,K/32).
// ---------------------------------------------------------------------------
__global__ __launch_bounds__(256)
void transpose_w(const float* __restrict__ W, __nv_bfloat16* __restrict__ Th,
                 __nv_bfloat16* __restrict__ Tl, int K, int N)
{
    __shared__ float tile[32][33];
    const int n0 = blockIdx.x * 32, k0 = blockIdx.y * 32;
    const int tx = threadIdx.x, ty = threadIdx.y;
    #pragma unroll
    for (int i = 0; i < 4; i++)
        tile[ty + i * 8][tx] = W[(size_t)(k0 + ty + i * 8) * N + n0 + tx];
    __syncthreads();
    #pragma unroll
    for (int i = 0; i < 4; i++) {
        int n = ty + i * 8;
        float v = tile[tx][n];
        __nv_bfloat16 h = __float2bfloat16(v);
        __nv_bfloat16 l = __float2bfloat16(v - __bfloat162float(h));
        size_t off = (size_t)(n0 + n) * K + k0 + tx;
        Th[off] = h;
        Tl[off] = l;
    }
}

// ---------------------------------------------------------------------------
// HMMA GEMM, 2-stage cp.async pipeline + ldmatrix fragment loads.
// C[4096,N] = A * W, bf16x3 split. CTA 128x128, 8 warps (2m x 4n), BK=32.
// MODE 0: plain fp32 -> C0. MODE 1: RoPE -> C0.
// MODE 3: fused kvdd (N=2048): sub = n0>>9 selects
//   0: RoPE -> C0[m][512], 1: plain -> C1[m][512],
//   2/3: (B,HK,T,D) transposed -> C2 / C3.
// ---------------------------------------------------------------------------
#define SA 40
#define GSTG 40960
#define GEMM_DYN (2 * GSTG)

template<int MODE>
__global__ __launch_bounds__(256, 2)
void gemm_mma(const __nv_bfloat16* __restrict__ AH, const __nv_bfloat16* __restrict__ AL,
              const __nv_bfloat16* __restrict__ BH, const __nv_bfloat16* __restrict__ BL,
              float* __restrict__ C0, float* __restrict__ C1,
              float* __restrict__ C2, float* __restrict__ C3, int N,
              const float* __restrict__ cosT, const float* __restrict__ sinT)
{
    extern __shared__ char gsm[];
    const uint32_t sb = smem_u32(gsm);
    const int tid = threadIdx.x;
    const int wid = tid >> 5, lane = tid & 31;
    const int g = lane >> 2, tig = lane & 3;
    const int wm = wid >> 2, wn = wid & 3;
    const int m0 = blockIdx.y * 128;
    const int n0 = blockIdx.x * 128;

    float acc[4][4][4];
    #pragma unroll
    for (int mt = 0; mt < 4; mt++)
        #pragma unroll
        for (int nt = 0; nt < 4; nt++)
            #pragma unroll
            for (int e = 0; e < 4; e++) acc[mt][nt][e] = 0.f;

    const int row = tid >> 2, part = tid & 3;
    const uint32_t so = (uint32_t)(row * SA + part * 8) * 2;

    // ldmatrix per-lane offsets (bytes).
    // A x4: lanes 0-7 m0-7/k0, 8-15 m8-15/k0, 16-23 m0-7/k8, 24-31 m8-15/k8.
    const int r8 = lane & 7;
    const int ahf = (lane >> 3) & 1, ak8 = (lane >> 4) & 1;
    uint32_t aoff[4];
    #pragma unroll
    for (int mt = 0; mt < 4; mt++)
        aoff[mt] = (uint32_t)(((wm * 64 + mt * 16 + ahf * 8 + r8) * SA + ak8 * 8) * 2);
    // B x4 (two n-tiles): lanes 0-7 nt/k0, 8-15 nt/k8, 16-23 nt+1/k0, 24-31 nt+1/k8.
    const int bk8 = (lane >> 3) & 1, ntp = (lane >> 4) & 1;
    uint32_t boff[2];
    #pragma unroll
    for (int np = 0; np < 2; np++)
        boff[np] = (uint32_t)(((wn * 32 + (np * 2 + ntp) * 8 + r8) * SA + bk8 * 8) * 2);

    // async load of one 32-K chunk into given stage
    auto issue_load = [&](int stage, int kc) {
        const int k0 = kc * 32;
        const uint32_t st = sb + stage * GSTG;
        #pragma unroll
        for (int it = 0; it < 2; it++) {
            int r2 = row + it * 64;
            size_t ga = (size_t)(m0 + r2) * KGEMM + k0 + part * 8;
            size_t gb = (size_t)(n0 + r2) * KGEMM + k0 + part * 8;
            uint32_t s2 = so + (uint32_t)(it * 64 * SA * 2);
            cpa16(st + s2,         AH + ga);
            cpa16(st + 10240 + s2, AL + ga);
            cpa16(st + 20480 + s2, BH + gb);
            cpa16(st + 30720 + s2, BL + gb);
        }
        CP_COMMIT;
    };

    const int nk = KGEMM / 32;   // 64
    issue_load(0, 0);

    for (int kc = 0; kc < nk; kc++) {
        const int st = kc & 1;
        if (kc + 1 < nk) { issue_load((kc + 1) & 1, kc + 1); CP_WAIT1; }
        else             { CP_WAIT0; }
        __syncthreads();

        const uint32_t stb = sb + st * GSTG;
        #pragma unroll
        for (int ks = 0; ks < 2; ks++) {
            const uint32_t ko = (uint32_t)(ks * 32);   // 16 bf16 = 32 bytes
            uint32_t bh2[2][4], bl2[2][4];
            ldsm4(bh2[0], stb + 20480 + boff[0] + ko);
            ldsm4(bh2[1], stb + 20480 + boff[1] + ko);
            ldsm4(bl2[0], stb + 30720 + boff[0] + ko);
            ldsm4(bl2[1], stb + 30720 + boff[1] + ko);

            uint32_t af[4][4];
            #pragma unroll
            for (int mt = 0; mt < 4; mt++)
                ldsm4(af[mt], stb + aoff[mt] + ko);
            #pragma unroll
            for (int mt = 0; mt < 4; mt++)
                #pragma unroll
                for (int nt = 0; nt < 4; nt++) {
                    mma16816(acc[mt][nt], af[mt], &bh2[nt >> 1][(nt & 1) * 2]);
                    mma16816(acc[mt][nt], af[mt], &bl2[nt >> 1][(nt & 1) * 2]);
                }
            #pragma unroll
            for (int mt = 0; mt < 4; mt++)
                ldsm4(af[mt], stb + 10240 + aoff[mt] + ko);
            #pragma unroll
            for (int mt = 0; mt < 4; mt++)
                #pragma unroll
                for (int nt = 0; nt < 4; nt++)
                    mma16816(acc[mt][nt], af[mt], &bh2[nt >> 1][(nt & 1) * 2]);
        }
        __syncthreads();
    }

    // Epilogue
    const int sub = n0 >> 9;   // uniform per CTA (used by MODE 3)
    #pragma unroll
    for (int mt = 0; mt < 4; mt++) {
        const int r0 = m0 + wm * 64 + mt * 16 + g;
        #pragma unroll
        for (int nt = 0; nt < 4; nt++) {
            const int n = n0 + wn * 32 + nt * 8 + 2 * tig;
            #pragma unroll
            for (int half = 0; half < 2; half++) {
                const int m = r0 + half * 8;
                float e = acc[mt][nt][half * 2 + 0];
                float o = acc[mt][nt][half * 2 + 1];
                const bool dorope = (MODE == 1) || (MODE == 3 && sub == 0);
                if (dorope) {
                    int t = m & (TT - 1);
                    int j0 = (n & (DD - 1)) >> 1;
                    float cc = cosT[(size_t)t * (DD / 2) + j0];
                    float ss = sinT[(size_t)t * (DD / 2) + j0];
                    float e2 = e * cc - o * ss;
                    o = e * ss + o * cc;
                    e = e2;
                }
                float2 vv = make_float2(e, o);
                if (MODE == 3) {
                    int nn = n & 511;
                    if (sub == 0) {
                        *reinterpret_cast<float2*>(&C0[(size_t)m * 512 + nn]) = vv;
                    } else if (sub == 1) {
                        *reinterpret_cast<float2*>(&C1[(size_t)m * 512 + nn]) = vv;
                    } else {
                        int b = m >> 11, t = m & (TT - 1);
                        int hk = nn >> 7, d = n & (DD - 1);
                        float* dst = (sub == 2) ? C2 : C3;
                        *reinterpret_cast<float2*>(
                            &dst[(((size_t)(b * HKK + hk) * TT + t) * DD) + d]) = vv;
                    }
                } else {
                    *reinterpret_cast<float2*>(&C0[(size_t)m * N + n]) = vv;
                }
            }
        }
    }
}

// ---------------------------------------------------------------------------
// HMMA flash attention, bf16x3 both stages (unchanged from R9/R10; known good).
// ---------------------------------------------------------------------------
#define QS 136
#define VS 72
#define ATT_SMEM ((2*128*QS + 2*64*QS + 2*128*VS) * 2)

__global__ __launch_bounds__(256, 1)
void attn_mma(const float* __restrict__ q, const float* __restrict__ k,
              const float* __restrict__ v,
              __nv_bfloat16* __restrict__ yh, __nv_bfloat16* __restrict__ yl)
{
    extern __shared__ __nv_bfloat16 smp[];
    __nv_bfloat16* Qh  = smp;
    __nv_bfloat16* Ql  = Qh + 128 * QS;
    __nv_bfloat16* Kh  = Ql + 128 * QS;
    __nv_bfloat16* Kl  = Kh + 64 * QS;
    __nv_bfloat16* VTh = Kl + 64 * QS;
    __nv_bfloat16* VTl = VTh + 128 * VS;

    const int it = blockIdx.x;
    const int h  = blockIdx.y;
    const int b  = blockIdx.z;
    const int gk = h >> 2;
    const int t0 = it * 128;
    const int tid = threadIdx.x;
    const int wm = tid >> 5, lane = tid & 31;
    const int g = lane >> 2, tig = lane & 3;
    const float scale = 0.08838834764831845f;

    for (int e = tid; e < 128 * 32; e += 256) {
        int row = e >> 5, c4 = (e & 31) << 2;
        float4 qv = *reinterpret_cast<const float4*>(
            &q[((size_t)(b * TT + t0 + row) * HH + h) * DD + c4]);
        uint32_t h0 = pack_hi2(qv.x, qv.y), h1 = pack_hi2(qv.z, qv.w);
        uint32_t l0 = pack_lo2(qv.x, qv.y, h0), l1 = pack_lo2(qv.z, qv.w, h1);
        *reinterpret_cast<uint2*>(&Qh[row * QS + c4]) = make_uint2(h0, h1);
        *reinterpret_cast<uint2*>(&Ql[row * QS + c4]) = make_uint2(l0, l1);
    }

    float o[16][4];
    #pragma unroll
    for (int dt = 0; dt < 16; dt++)
        #pragma unroll
        for (int e = 0; e < 4; e++) o[dt][e] = 0.f;
    float m0r = -INFINITY, m1r = -INFINITY, l0r = 0.f, l1r = 0.f;

    const int njt = 2 * it + 2;
    for (int jt = 0; jt < njt; jt++) {
        const int s0 = jt * 64;
        __syncthreads();

        for (int e = tid; e < 64 * 32; e += 256) {
            int row = e >> 5, c4 = (e & 31) << 2;
            float4 kv = *reinterpret_cast<const float4*>(
                &k[((size_t)(b * TT + s0 + row) * HKK + gk) * DD + c4]);
            uint32_t h0 = pack_hi2(kv.x, kv.y), h1 = pack_hi2(kv.z, kv.w);
            uint32_t l0 = pack_lo2(kv.x, kv.y, h0), l1 = pack_lo2(kv.z, kv.w, h1);
            *reinterpret_cast<uint2*>(&Kh[row * QS + c4]) = make_uint2(h0, h1);
            *reinterpret_cast<uint2*>(&Kl[row * QS + c4]) = make_uint2(l0, l1);
        }
        {
            const int d = tid & 127, sb2 = (tid >> 7) * 32;
            const float* vb = &v[((size_t)(b * TT + s0 + sb2) * HKK + gk) * DD + d];
            #pragma unroll
            for (int i = 0; i < 8; i++) {
                float v0 = vb[(size_t)(i * 4 + 0) * HKK * DD];
                float v1 = vb[(size_t)(i * 4 + 1) * HKK * DD];
                float v2 = vb[(size_t)(i * 4 + 2) * HKK * DD];
                float v3 = vb[(size_t)(i * 4 + 3) * HKK * DD];
                uint32_t h0 = pack_hi2(v0, v1), h1 = pack_hi2(v2, v3);
                uint32_t l0 = pack_lo2(v0, v1, h0), l1 = pack_lo2(v2, v3, h1);
                int so = d * VS + sb2 + i * 4;
                *reinterpret_cast<uint2*>(&VTh[so]) = make_uint2(h0, h1);
                *reinterpret_cast<uint2*>(&VTl[so]) = make_uint2(l0, l1);
            }
        }
        __syncthreads();

        float sc[8][4];
        #pragma unroll
        for (int nt = 0; nt < 8; nt++)
            #pragma unroll
            for (int e = 0; e < 4; e++) sc[nt][e] = 0.f;

        #pragma unroll
        for (int kk = 0; kk < 8; kk++) {
            const int kcol = kk * 16 + 2 * tig;
            const int ar = (wm * 16 + g) * QS;
            uint32_t ah[4], al[4];
            ah[0] = *reinterpret_cast<const uint32_t*>(&Qh[ar + kcol]);
            ah[1] = *reinterpret_cast<const uint32_t*>(&Qh[ar + 8 * QS + kcol]);
            ah[2] = *reinterpret_cast<const uint32_t*>(&Qh[ar + kcol + 8]);
            ah[3] = *reinterpret_cast<const uint32_t*>(&Qh[ar + 8 * QS + kcol + 8]);
            al[0] = *reinterpret_cast<const uint32_t*>(&Ql[ar + kcol]);
            al[1] = *reinterpret_cast<const uint32_t*>(&Ql[ar + 8 * QS + kcol]);
            al[2] = *reinterpret_cast<const uint32_t*>(&Ql[ar + kcol + 8]);
            al[3] = *reinterpret_cast<const uint32_t*>(&Ql[ar + 8 * QS + kcol + 8]);
            #pragma unroll
            for (int nt = 0; nt < 8; nt++) {
                const int br = (nt * 8 + g) * QS;
                uint32_t bh[2], bl[2];
                bh[0] = *reinterpret_cast<const uint32_t*>(&Kh[br + kcol]);
                bh[1] = *reinterpret_cast<const uint32_t*>(&Kh[br + kcol + 8]);
                bl[0] = *reinterpret_cast<const uint32_t*>(&Kl[br + kcol]);
                bl[1] = *reinterpret_cast<const uint32_t*>(&Kl[br + kcol + 8]);
                mma16816(sc[nt], ah, bh);
                mma16816(sc[nt], ah, bl);
                mma16816(sc[nt], al, bh);
            }
        }

        const int row0 = t0 + wm * 16 + g;
        const bool needmask = (s0 + 63 > row0);
        float mx0 = -INFINITY, mx1 = -INFINITY;
        #pragma unroll
        for (int nt = 0; nt < 8; nt++) {
            #pragma unroll
            for (int e = 0; e < 4; e++) sc[nt][e] *= scale;
            if (needmask) {
                int c0 = s0 + nt * 8 + 2 * tig;
                if (c0     > row0)     sc[nt][0] = -INFINITY;
                if (c0 + 1 > row0)     sc[nt][1] = -INFINITY;
                if (c0     > row0 + 8) sc[nt][2] = -INFINITY;
                if (c0 + 1 > row0 + 8) sc[nt][3] = -INFINITY;
            }
            mx0 = fmaxf(mx0, fmaxf(sc[nt][0], sc[nt][1]));
            mx1 = fmaxf(mx1, fmaxf(sc[nt][2], sc[nt][3]));
        }
        #pragma unroll
        for (int msk = 1; msk < 4; msk <<= 1) {
            mx0 = fmaxf(mx0, __shfl_xor_sync(0xffffffffu, mx0, msk));
            mx1 = fmaxf(mx1, __shfl_xor_sync(0xffffffffu, mx1, msk));
        }
        float mn0 = fmaxf(m0r, mx0), mn1 = fmaxf(m1r, mx1);
        float f0 = __expf(m0r - mn0), f1 = __expf(m1r - mn1);
        float s0s = 0.f, s1s = 0.f;
        #pragma unroll
        for (int nt = 0; nt < 8; nt++) {
            float p0 = __expf(sc[nt][0] - mn0); sc[nt][0] = p0; s0s += p0;
            float p1 = __expf(sc[nt][1] - mn0); sc[nt][1] = p1; s0s += p1;
            float p2 = __expf(sc[nt][2] - mn1); sc[nt][2] = p2; s1s += p2;
            float p3 = __expf(sc[nt][3] - mn1); sc[nt][3] = p3; s1s += p3;
        }
        #pragma unroll
        for (int msk = 1; msk < 4; msk <<= 1) {
            s0s += __shfl_xor_sync(0xffffffffu, s0s, msk);
            s1s += __shfl_xor_sync(0xffffffffu, s1s, msk);
        }
        l0r = l0r * f0 + s0s; l1r = l1r * f1 + s1s;
        m0r = mn0; m1r = mn1;
        #pragma unroll
        for (int dt = 0; dt < 16; dt++) {
            o[dt][0] *= f0; o[dt][1] *= f0;
            o[dt][2] *= f1; o[dt][3] *= f1;
        }

        #pragma unroll
        for (int kks = 0; kks < 4; kks++) {
            uint32_t pha[4], pla[4];
            pha[0] = pack_hi2(sc[2*kks][0],   sc[2*kks][1]);
            pla[0] = pack_lo2(sc[2*kks][0],   sc[2*kks][1],   pha[0]);
            pha[1] = pack_hi2(sc[2*kks][2],   sc[2*kks][3]);
            pla[1] = pack_lo2(sc[2*kks][2],   sc[2*kks][3],   pha[1]);
            pha[2] = pack_hi2(sc[2*kks+1][0], sc[2*kks+1][1]);
            pla[2] = pack_lo2(sc[2*kks+1][0], sc[2*kks+1][1], pha[2]);
            pha[3] = pack_hi2(sc[2*kks+1][2], sc[2*kks+1][3]);
            pla[3] = pack_lo2(sc[2*kks+1][2], sc[2*kks+1][3], pha[3]);
            #pragma unroll
            for (int dt = 0; dt < 16; dt++) {
                const int br = (dt * 8 + g) * VS + kks * 16 + 2 * tig;
                uint32_t bh[2], bl[2];
                bh[0] = *reinterpret_cast<const uint32_t*>(&VTh[br]);
                bh[1] = *reinterpret_cast<const uint32_t*>(&VTh[br + 8]);
                bl[0] = *reinterpret_cast<const uint32_t*>(&VTl[br]);
                bl[1] = *reinterpret_cast<const uint32_t*>(&VTl[br + 8]);
                mma16816(o[dt], pha, bh);
                mma16816(o[dt], pha, bl);
                mma16816(o[dt], pla, bh);
            }
        }
    }

    const float inv0 = 1.f / l0r, inv1 = 1.f / l1r;
    const int row0 = t0 + wm * 16 + g;
    #pragma unroll
    for (int dt = 0; dt < 16; dt++) {
        int d = dt * 8 + 2 * tig;
        size_t b0 = ((size_t)(b * TT + row0) * HH + h) * DD + d;
        size_t b1 = ((size_t)(b * TT + row0 + 8) * HH + h) * DD + d;
        uint32_t h0 = pack_hi2(o[dt][0] * inv0, o[dt][1] * inv0);
        uint32_t l0 = pack_lo2(o[dt][0] * inv0, o[dt][1] * inv0, h0);
        uint32_t h1 = pack_hi2(o[dt][2] * inv1, o[dt][3] * inv1);
        uint32_t l1 = pack_lo2(o[dt][2] * inv1, o[dt][3] * inv1, h1);
        *reinterpret_cast<uint32_t*>(&yh[b0]) = h0;
        *reinterpret_cast<uint32_t*>(&yl[b0]) = l0;
        *reinterpret_cast<uint32_t*>(&yh[b1]) = h1;
        *reinterpret_cast<uint32_t*>(&yl[b1]) = l1;
    }
}

// ---------------------------------------------------------------------------
// Launch
// ---------------------------------------------------------------------------
extern "C" void kernel_launch(void* const* d_in, const int* in_sizes, int n_in,
                              void* d_out, int out_size)
{
    const float* x      = (const float*)d_in[0];
    const float* w_q    = (const float*)d_in[1];
    const float* w_k    = (const float*)d_in[2];
    const float* w_v    = (const float*)d_in[3];
    const float* w_proj = (const float*)d_in[4];
    const float* w_dk   = (const float*)d_in[5];
    const float* w_dv   = (const float*)d_in[6];
    const float* fcos   = (const float*)d_in[7];
    const float* fsin   = (const float*)d_in[8];

    float* out    = (float*)d_out;
    float* out_y  = out;
    float* out_kw = out + (size_t)BB * TT * CCH;
    float* out_vw = out_kw + (size_t)BB * HKK * TT * DD;

    static float *pq = nullptr, *pk = nullptr, *pv = nullptr;
    static __nv_bfloat16 *xh, *xl, *yh, *yl, *wh, *wl;
    if (!pq) {
        cudaGetSymbolAddress((void**)&pq, g_q);
        cudaGetSymbolAddress((void**)&pk, g_k);
        cudaGetSymbolAddress((void**)&pv, g_v);
        cudaGetSymbolAddress((void**)&xh, g_xh);
        cudaGetSymbolAddress((void**)&xl, g_xl);
        cudaGetSymbolAddress((void**)&yh, g_yh);
        cudaGetSymbolAddress((void**)&yl, g_yl);
        cudaGetSymbolAddress((void**)&wh, g_wh);
        cudaGetSymbolAddress((void**)&wl, g_wl);
        cudaFuncSetAttribute(attn_mma,
                             cudaFuncAttributeMaxDynamicSharedMemorySize, ATT_SMEM);
        cudaFuncSetAttribute(gemm_mma<0>,
                             cudaFuncAttributeMaxDynamicSharedMemorySize, GEMM_DYN);
        cudaFuncSetAttribute(gemm_mma<1>,
                             cudaFuncAttributeMaxDynamicSharedMemorySize, GEMM_DYN);
        cudaFuncSetAttribute(gemm_mma<3>,
                             cudaFuncAttributeMaxDynamicSharedMemorySize, GEMM_DYN);
    }

    // 1) split x into bf16 hi/lo
    split_f32<<<(MR * CCH / 4 + 255) / 256, 256>>>(x, xh, xl, MR * CCH / 4);
    // 2) transpose + split weights (k,v,dk,dv contiguous at WK_OFF)
    dim3 tb(32, 8);
    transpose_w<<<dim3(CCH / 32, CCH / 32), tb>>>(w_q,    wh + WQ_OFF,            wl + WQ_OFF,            CCH, CCH);
    transpose_w<<<dim3(512 / 32, CCH / 32), tb>>>(w_k,    wh + WK_OFF,            wl + WK_OFF,            CCH, 512);
    transpose_w<<<dim3(512 / 32, CCH / 32), tb>>>(w_v,    wh + WK_OFF + 1048576,  wl + WK_OFF + 1048576,  CCH, 512);
    transpose_w<<<dim3(512 / 32, CCH / 32), tb>>>(w_dk,   wh + WK_OFF + 2097152,  wl + WK_OFF + 2097152,  CCH, 512);
    transpose_w<<<dim3(512 / 32, CCH / 32), tb>>>(w_dv,   wh + WK_OFF + 3145728,  wl + WK_OFF + 3145728,  CCH, 512);
    transpose_w<<<dim3(CCH / 32, CCH / 32), tb>>>(w_proj, wh + WP_OFF,            wl + WP_OFF,            CCH, CCH);

    dim3 blk(256);
    const int MT = MR / 128;
    // 3) q projection + fused k/v/dk/dv projection (HMMA bf16x3, cp.async)
    gemm_mma<1><<<dim3(16, MT), blk, GEMM_DYN>>>(xh, xl, wh + WQ_OFF, wl + WQ_OFF,
                                                 pq, 0, 0, 0, CCH, fcos, fsin);
    gemm_mma<3><<<dim3(16, MT), blk, GEMM_DYN>>>(xh, xl, wh + WK_OFF, wl + WK_OFF,
                                                 pk, pv, out_kw, out_vw, 2048, fcos, fsin);
    // 4) attention (HMMA bf16x3) -> y bf16 hi/lo
    attn_mma<<<dim3(TT / 128, HH, BB), blk, ATT_SMEM>>>(pq, pk, pv, yh, yl);
    // 5) output projection
    gemm_mma<0><<<dim3(16, MT), blk, GEMM_DYN>>>(yh, yl, wh + WP_OFF, wl + WP_OFF,
                                                 out_y, 0, 0, 0, CCH, 0, 0);
}

// round 15
// speedup vs baseline: 3.2222x; 1.0054x over previous
#include <cuda_runtime.h>
#include <cuda_bf16.h>
#include <math.h>
#include <stdint.h>

// Problem constants
#define BB   2
#define TT   2048
#define CCH  2048
#define HH   16
#define HKK  4
#define DD   128
#define MR   (BB*TT)          // 4096 rows
#define KGEMM 2048            // K of every GEMM here

// Weight scratch offsets (bf16 transposed [N][K]); k,v,dk,dv contiguous
#define WQ_OFF  0u
#define WK_OFF  4194304u
#define WP_OFF  8388608u
#define WTOT    12582912u

// ---------------------------------------------------------------------------
// Scratch (device globals; no allocation allowed)
// ---------------------------------------------------------------------------
__device__ float g_q[(size_t)BB*TT*HH*DD];      // (B,T,H*D) after RoPE (fp32)
__device__ float g_k[(size_t)BB*TT*HKK*DD];     // (B,T,HK*D) after RoPE
__device__ float g_v[(size_t)BB*TT*HKK*DD];     // (B,T,HK*D)
__device__ __nv_bfloat16 g_xh[(size_t)MR*CCH], g_xl[(size_t)MR*CCH];
__device__ __nv_bfloat16 g_yh[(size_t)MR*CCH], g_yl[(size_t)MR*CCH];
__device__ __nv_bfloat16 g_wh[WTOT], g_wl[WTOT];

// ---------------------------------------------------------------------------
// mma.sync m16n8k16 bf16 + helpers
// ---------------------------------------------------------------------------
__device__ __forceinline__ void mma16816(float* c, const uint32_t* a, const uint32_t* b)
{
    asm volatile(
        "mma.sync.aligned.m16n8k16.row.col.f32.bf16.bf16.f32 "
        "{%0,%1,%2,%3}, {%4,%5,%6,%7}, {%8,%9}, {%0,%1,%2,%3};\n"
        : "+f"(c[0]), "+f"(c[1]), "+f"(c[2]), "+f"(c[3])
        : "r"(a[0]), "r"(a[1]), "r"(a[2]), "r"(a[3]), "r"(b[0]), "r"(b[1]));
}

__device__ __forceinline__ void ldsm4(uint32_t* d, uint32_t addr)
{
    asm volatile("ldmatrix.sync.aligned.m8n8.x4.shared.b16 {%0,%1,%2,%3}, [%4];"
        : "=r"(d[0]), "=r"(d[1]), "=r"(d[2]), "=r"(d[3]) : "r"(addr));
}

__device__ __forceinline__ uint32_t pack_hi2(float a, float b)
{
    __nv_bfloat162 h = __floats2bfloat162_rn(a, b);
    return *reinterpret_cast<uint32_t*>(&h);
}
__device__ __forceinline__ uint32_t pack_lo2(float a, float b, uint32_t hi)
{
    __nv_bfloat162 h = *reinterpret_cast<__nv_bfloat162*>(&hi);
    __nv_bfloat162 l = __floats2bfloat162_rn(a - __bfloat162float(h.x),
                                             b - __bfloat162float(h.y));
    return *reinterpret_cast<uint32_t*>(&l);
}
__device__ __forceinline__ uint32_t smem_u32(const void* p)
{
    uint32_t a;
    asm("{ .reg .u64 t; cvta.to.shared.u64 t, %1; cvt.u32.u64 %0, t; }"
        : "=r"(a) : "l"(p));
    return a;
}
__device__ __forceinline__ void cpa16(uint32_t s, const void* g)
{
    asm volatile("cp.async.cg.shared.global [%0], [%1], 16;" :: "r"(s), "l"(g));
}
#define CP_COMMIT asm volatile("cp.async.commit_group;" ::: "memory")
#define CP_WAIT1  asm volatile("cp.async.wait_group 1;" ::: "memory")
#define CP_WAIT0  asm volatile("cp.async.wait_group 0;" ::: "memory")

// ---------------------------------------------------------------------------
// Split fp32 -> bf16 hi/lo (elementwise, vectorized)
// ---------------------------------------------------------------------------
__global__ __launch_bounds__(256)
void split_f32(const float* __restrict__ s, __nv_bfloat16* __restrict__ dh,
               __nv_bfloat16* __restrict__ dl, int n4)
{
    int i = blockIdx.x * blockDim.x + threadIdx.x;
    if (i >= n4) return;
    float4 v = reinterpret_cast<const float4*>(s)[i];
    uint32_t h0 = pack_hi2(v.x, v.y), h1 = pack_hi2(v.z, v.w);
    uint32_t l0 = pack_lo2(v.x, v.y, h0), l1 = pack_lo2(v.z, v.w, h1);
    reinterpret_cast<uint2*>(dh)[i] = make_uint2(h0, h1);
    reinterpret_cast<uint2*>(dl)[i] = make_uint2(l0, l1);
}

// ---------------------------------------------------------------------------
// Transpose W[K][N] fp32 -> Wt[N][K] bf16 hi/lo. Block (32,8), grid (N/32,K/32).
// ---------------------------------------------------------------------------
__global__ __launch_bounds__(256)
void transpose_w(const float* __restrict__ W, __nv_bfloat16* __restrict__ Th,
                 __nv_bfloat16* __restrict__ Tl, int K, int N)
{
    __shared__ float tile[32][33];
    const int n0 = blockIdx.x * 32, k0 = blockIdx.y * 32;
    const int tx = threadIdx.x, ty = threadIdx.y;
    #pragma unroll
    for (int i = 0; i < 4; i++)
        tile[ty + i * 8][tx] = W[(size_t)(k0 + ty + i * 8) * N + n0 + tx];
    __syncthreads();
    #pragma unroll
    for (int i = 0; i < 4; i++) {
        int n = ty + i * 8;
        float v = tile[tx][n];
        __nv_bfloat16 h = __float2bfloat16(v);
        __nv_bfloat16 l = __float2bfloat16(v - __bfloat162float(h));
        size_t off = (size_t)(n0 + n) * K + k0 + tx;
        Th[off] = h;
        Tl[off] = l;
    }
}

// ---------------------------------------------------------------------------
// Merged transpose for the 4 x 512-wide weights (k,v,dk,dv) -> one [2048][K].
// grid (64, K/32); blockIdx.x selects source by 512-column range.
// ---------------------------------------------------------------------------
__global__ __launch_bounds__(256)
void transpose_kvdd(const float* __restrict__ Wk, const float* __restrict__ Wv,
                    const float* __restrict__ Wdk, const float* __restrict__ Wdv,
                    __nv_bfloat16* __restrict__ Th, __nv_bfloat16* __restrict__ Tl)
{
    __shared__ float tile[32][33];
    const int sel = blockIdx.x >> 4;              // 0..3
    const float* W = (sel == 0) ? Wk : (sel == 1) ? Wv : (sel == 2) ? Wdk : Wdv;
    const int n0l = (blockIdx.x & 15) * 32;       // local col within its weight
    const int gn0 = blockIdx.x * 32;              // global dst row
    const int k0 = blockIdx.y * 32;
    const int tx = threadIdx.x, ty = threadIdx.y;
    #pragma unroll
    for (int i = 0; i < 4; i++)
        tile[ty + i * 8][tx] = W[(size_t)(k0 + ty + i * 8) * 512 + n0l + tx];
    __syncthreads();
    #pragma unroll
    for (int i = 0; i < 4; i++) {
        int n = ty + i * 8;
        float v = tile[tx][n];
        __nv_bfloat16 h = __float2bfloat16(v);
        __nv_bfloat16 l = __float2bfloat16(v - __bfloat162float(h));
        size_t off = (size_t)(gn0 + n) * KGEMM + k0 + tx;
        Th[off] = h;
        Tl[off] = l;
    }
}

// ---------------------------------------------------------------------------
// HMMA GEMM, 2-stage cp.async pipeline + ldmatrix fragment loads.
// (byte-identical body to the 1538us kernel)
// ---------------------------------------------------------------------------
#define SA 40
#define GSTG 40960
#define GEMM_DYN (2 * GSTG)

template<int MODE>
__global__ __launch_bounds__(256, 2)
void gemm_mma(const __nv_bfloat16* __restrict__ AH, const __nv_bfloat16* __restrict__ AL,
              const __nv_bfloat16* __restrict__ BH, const __nv_bfloat16* __restrict__ BL,
              float* __restrict__ C0, float* __restrict__ C1,
              float* __restrict__ C2, float* __restrict__ C3, int N,
              const float* __restrict__ cosT, const float* __restrict__ sinT)
{
    extern __shared__ char gsm[];
    const uint32_t sb = smem_u32(gsm);
    const int tid = threadIdx.x;
    const int wid = tid >> 5, lane = tid & 31;
    const int g = lane >> 2, tig = lane & 3;
    const int wm = wid >> 2, wn = wid & 3;
    const int m0 = blockIdx.y * 128;
    const int n0 = blockIdx.x * 128;

    float acc[4][4][4];
    #pragma unroll
    for (int mt = 0; mt < 4; mt++)
        #pragma unroll
        for (int nt = 0; nt < 4; nt++)
            #pragma unroll
            for (int e = 0; e < 4; e++) acc[mt][nt][e] = 0.f;

    const int row = tid >> 2, part = tid & 3;
    const uint32_t so = (uint32_t)(row * SA + part * 8) * 2;

    const int r8 = lane & 7;
    const int ahf = (lane >> 3) & 1, ak8 = (lane >> 4) & 1;
    uint32_t aoff[4];
    #pragma unroll
    for (int mt = 0; mt < 4; mt++)
        aoff[mt] = (uint32_t)(((wm * 64 + mt * 16 + ahf * 8 + r8) * SA + ak8 * 8) * 2);
    const int bk8 = (lane >> 3) & 1, ntp = (lane >> 4) & 1;
    uint32_t boff[2];
    #pragma unroll
    for (int np = 0; np < 2; np++)
        boff[np] = (uint32_t)(((wn * 32 + (np * 2 + ntp) * 8 + r8) * SA + bk8 * 8) * 2);

    auto issue_load = [&](int stage, int kc) {
        const int k0 = kc * 32;
        const uint32_t st = sb + stage * GSTG;
        #pragma unroll
        for (int it = 0; it < 2; it++) {
            int r2 = row + it * 64;
            size_t ga = (size_t)(m0 + r2) * KGEMM + k0 + part * 8;
            size_t gb = (size_t)(n0 + r2) * KGEMM + k0 + part * 8;
            uint32_t s2 = so + (uint32_t)(it * 64 * SA * 2);
            cpa16(st + s2,         AH + ga);
            cpa16(st + 10240 + s2, AL + ga);
            cpa16(st + 20480 + s2, BH + gb);
            cpa16(st + 30720 + s2, BL + gb);
        }
        CP_COMMIT;
    };

    const int nk = KGEMM / 32;   // 64
    issue_load(0, 0);

    for (int kc = 0; kc < nk; kc++) {
        const int st = kc & 1;
        if (kc + 1 < nk) { issue_load((kc + 1) & 1, kc + 1); CP_WAIT1; }
        else             { CP_WAIT0; }
        __syncthreads();

        const uint32_t stb = sb + st * GSTG;
        #pragma unroll
        for (int ks = 0; ks < 2; ks++) {
            const uint32_t ko = (uint32_t)(ks * 32);
            uint32_t bh2[2][4], bl2[2][4];
            ldsm4(bh2[0], stb + 20480 + boff[0] + ko);
            ldsm4(bh2[1], stb + 20480 + boff[1] + ko);
            ldsm4(bl2[0], stb + 30720 + boff[0] + ko);
            ldsm4(bl2[1], stb + 30720 + boff[1] + ko);

            uint32_t af[4][4];
            #pragma unroll
            for (int mt = 0; mt < 4; mt++)
                ldsm4(af[mt], stb + aoff[mt] + ko);
            #pragma unroll
            for (int mt = 0; mt < 4; mt++)
                #pragma unroll
                for (int nt = 0; nt < 4; nt++) {
                    mma16816(acc[mt][nt], af[mt], &bh2[nt >> 1][(nt & 1) * 2]);
                    mma16816(acc[mt][nt], af[mt], &bl2[nt >> 1][(nt & 1) * 2]);
                }
            #pragma unroll
            for (int mt = 0; mt < 4; mt++)
                ldsm4(af[mt], stb + 10240 + aoff[mt] + ko);
            #pragma unroll
            for (int mt = 0; mt < 4; mt++)
                #pragma unroll
                for (int nt = 0; nt < 4; nt++)
                    mma16816(acc[mt][nt], af[mt], &bh2[nt >> 1][(nt & 1) * 2]);
        }
        __syncthreads();
    }

    const int sub = n0 >> 9;
    #pragma unroll
    for (int mt = 0; mt < 4; mt++) {
        const int r0 = m0 + wm * 64 + mt * 16 + g;
        #pragma unroll
        for (int nt = 0; nt < 4; nt++) {
            const int n = n0 + wn * 32 + nt * 8 + 2 * tig;
            #pragma unroll
            for (int half = 0; half < 2; half++) {
                const int m = r0 + half * 8;
                float e = acc[mt][nt][half * 2 + 0];
                float o = acc[mt][nt][half * 2 + 1];
                const bool dorope = (MODE == 1) || (MODE == 3 && sub == 0);
                if (dorope) {
                    int t = m & (TT - 1);
                    int j0 = (n & (DD - 1)) >> 1;
                    float cc = cosT[(size_t)t * (DD / 2) + j0];
                    float ss = sinT[(size_t)t * (DD / 2) + j0];
                    float e2 = e * cc - o * ss;
                    o = e * ss + o * cc;
                    e = e2;
                }
                float2 vv = make_float2(e, o);
                if (MODE == 3) {
                    int nn = n & 511;
                    if (sub == 0) {
                        *reinterpret_cast<float2*>(&C0[(size_t)m * 512 + nn]) = vv;
                    } else if (sub == 1) {
                        *reinterpret_cast<float2*>(&C1[(size_t)m * 512 + nn]) = vv;
                    } else {
                        int b = m >> 11, t = m & (TT - 1);
                        int hk = nn >> 7, d = n & (DD - 1);
                        float* dst = (sub == 2) ? C2 : C3;
                        *reinterpret_cast<float2*>(
                            &dst[(((size_t)(b * HKK + hk) * TT + t) * DD) + d]) = vv;
                    }
                } else {
                    *reinterpret_cast<float2*>(&C0[(size_t)m * N + n]) = vv;
                }
            }
        }
    }
}

// ---------------------------------------------------------------------------
// HMMA flash attention, bf16x3 both stages (byte-identical; known good).
// ---------------------------------------------------------------------------
#define QS 136
#define VS 72
#define ATT_SMEM ((2*128*QS + 2*64*QS + 2*128*VS) * 2)

__global__ __launch_bounds__(256, 1)
void attn_mma(const float* __restrict__ q, const float* __restrict__ k,
              const float* __restrict__ v,
              __nv_bfloat16* __restrict__ yh, __nv_bfloat16* __restrict__ yl)
{
    extern __shared__ __nv_bfloat16 smp[];
    __nv_bfloat16* Qh  = smp;
    __nv_bfloat16* Ql  = Qh + 128 * QS;
    __nv_bfloat16* Kh  = Ql + 128 * QS;
    __nv_bfloat16* Kl  = Kh + 64 * QS;
    __nv_bfloat16* VTh = Kl + 64 * QS;
    __nv_bfloat16* VTl = VTh + 128 * VS;

    const int it = blockIdx.x;
    const int h  = blockIdx.y;
    const int b  = blockIdx.z;
    const int gk = h >> 2;
    const int t0 = it * 128;
    const int tid = threadIdx.x;
    const int wm = tid >> 5, lane = tid & 31;
    const int g = lane >> 2, tig = lane & 3;
    const float scale = 0.08838834764831845f;

    for (int e = tid; e < 128 * 32; e += 256) {
        int row = e >> 5, c4 = (e & 31) << 2;
        float4 qv = *reinterpret_cast<const float4*>(
            &q[((size_t)(b * TT + t0 + row) * HH + h) * DD + c4]);
        uint32_t h0 = pack_hi2(qv.x, qv.y), h1 = pack_hi2(qv.z, qv.w);
        uint32_t l0 = pack_lo2(qv.x, qv.y, h0), l1 = pack_lo2(qv.z, qv.w, h1);
        *reinterpret_cast<uint2*>(&Qh[row * QS + c4]) = make_uint2(h0, h1);
        *reinterpret_cast<uint2*>(&Ql[row * QS + c4]) = make_uint2(l0, l1);
    }

    float o[16][4];
    #pragma unroll
    for (int dt = 0; dt < 16; dt++)
        #pragma unroll
        for (int e = 0; e < 4; e++) o[dt][e] = 0.f;
    float m0r = -INFINITY, m1r = -INFINITY, l0r = 0.f, l1r = 0.f;

    const int njt = 2 * it + 2;
    for (int jt = 0; jt < njt; jt++) {
        const int s0 = jt * 64;
        __syncthreads();

        for (int e = tid; e < 64 * 32; e += 256) {
            int row = e >> 5, c4 = (e & 31) << 2;
            float4 kv = *reinterpret_cast<const float4*>(
                &k[((size_t)(b * TT + s0 + row) * HKK + gk) * DD + c4]);
            uint32_t h0 = pack_hi2(kv.x, kv.y), h1 = pack_hi2(kv.z, kv.w);
            uint32_t l0 = pack_lo2(kv.x, kv.y, h0), l1 = pack_lo2(kv.z, kv.w, h1);
            *reinterpret_cast<uint2*>(&Kh[row * QS + c4]) = make_uint2(h0, h1);
            *reinterpret_cast<uint2*>(&Kl[row * QS + c4]) = make_uint2(l0, l1);
        }
        {
            const int d = tid & 127, sb2 = (tid >> 7) * 32;
            const float* vb = &v[((size_t)(b * TT + s0 + sb2) * HKK + gk) * DD + d];
            #pragma unroll
            for (int i = 0; i < 8; i++) {
                float v0 = vb[(size_t)(i * 4 + 0) * HKK * DD];
                float v1 = vb[(size_t)(i * 4 + 1) * HKK * DD];
                float v2 = vb[(size_t)(i * 4 + 2) * HKK * DD];
                float v3 = vb[(size_t)(i * 4 + 3) * HKK * DD];
                uint32_t h0 = pack_hi2(v0, v1), h1 = pack_hi2(v2, v3);
                uint32_t l0 = pack_lo2(v0, v1, h0), l1 = pack_lo2(v2, v3, h1);
                int so = d * VS + sb2 + i * 4;
                *reinterpret_cast<uint2*>(&VTh[so]) = make_uint2(h0, h1);
                *reinterpret_cast<uint2*>(&VTl[so]) = make_uint2(l0, l1);
            }
        }
        __syncthreads();

        float sc[8][4];
        #pragma unroll
        for (int nt = 0; nt < 8; nt++)
            #pragma unroll
            for (int e = 0; e < 4; e++) sc[nt][e] = 0.f;

        #pragma unroll
        for (int kk = 0; kk < 8; kk++) {
            const int kcol = kk * 16 + 2 * tig;
            const int ar = (wm * 16 + g) * QS;
            uint32_t ah[4], al[4];
            ah[0] = *reinterpret_cast<const uint32_t*>(&Qh[ar + kcol]);
            ah[1] = *reinterpret_cast<const uint32_t*>(&Qh[ar + 8 * QS + kcol]);
            ah[2] = *reinterpret_cast<const uint32_t*>(&Qh[ar + kcol + 8]);
            ah[3] = *reinterpret_cast<const uint32_t*>(&Qh[ar + 8 * QS + kcol + 8]);
            al[0] = *reinterpret_cast<const uint32_t*>(&Ql[ar + kcol]);
            al[1] = *reinterpret_cast<const uint32_t*>(&Ql[ar + 8 * QS + kcol]);
            al[2] = *reinterpret_cast<const uint32_t*>(&Ql[ar + kcol + 8]);
            al[3] = *reinterpret_cast<const uint32_t*>(&Ql[ar + 8 * QS + kcol + 8]);
            #pragma unroll
            for (int nt = 0; nt < 8; nt++) {
                const int br = (nt * 8 + g) * QS;
                uint32_t bh[2], bl[2];
                bh[0] = *reinterpret_cast<const uint32_t*>(&Kh[br + kcol]);
                bh[1] = *reinterpret_cast<const uint32_t*>(&Kh[br + kcol + 8]);
                bl[0] = *reinterpret_cast<const uint32_t*>(&Kl[br + kcol]);
                bl[1] = *reinterpret_cast<const uint32_t*>(&Kl[br + kcol + 8]);
                mma16816(sc[nt], ah, bh);
                mma16816(sc[nt], ah, bl);
                mma16816(sc[nt], al, bh);
            }
        }

        const int row0 = t0 + wm * 16 + g;
        const bool needmask = (s0 + 63 > row0);
        float mx0 = -INFINITY, mx1 = -INFINITY;
        #pragma unroll
        for (int nt = 0; nt < 8; nt++) {
            #pragma unroll
            for (int e = 0; e < 4; e++) sc[nt][e] *= scale;
            if (needmask) {
                int c0 = s0 + nt * 8 + 2 * tig;
                if (c0     > row0)     sc[nt][0] = -INFINITY;
                if (c0 + 1 > row0)     sc[nt][1] = -INFINITY;
                if (c0     > row0 + 8) sc[nt][2] = -INFINITY;
                if (c0 + 1 > row0 + 8) sc[nt][3] = -INFINITY;
            }
            mx0 = fmaxf(mx0, fmaxf(sc[nt][0], sc[nt][1]));
            mx1 = fmaxf(mx1, fmaxf(sc[nt][2], sc[nt][3]));
        }
        #pragma unroll
        for (int msk = 1; msk < 4; msk <<= 1) {
            mx0 = fmaxf(mx0, __shfl_xor_sync(0xffffffffu, mx0, msk));
            mx1 = fmaxf(mx1, __shfl_xor_sync(0xffffffffu, mx1, msk));
        }
        float mn0 = fmaxf(m0r, mx0), mn1 = fmaxf(m1r, mx1);
        float f0 = __expf(m0r - mn0), f1 = __expf(m1r - mn1);
        float s0s = 0.f, s1s = 0.f;
        #pragma unroll
        for (int nt = 0; nt < 8; nt++) {
            float p0 = __expf(sc[nt][0] - mn0); sc[nt][0] = p0; s0s += p0;
            float p1 = __expf(sc[nt][1] - mn0); sc[nt][1] = p1; s0s += p1;
            float p2 = __expf(sc[nt][2] - mn1); sc[nt][2] = p2; s1s += p2;
            float p3 = __expf(sc[nt][3] - mn1); sc[nt][3] = p3; s1s += p3;
        }
        #pragma unroll
        for (int msk = 1; msk < 4; msk <<= 1) {
            s0s += __shfl_xor_sync(0xffffffffu, s0s, msk);
            s1s += __shfl_xor_sync(0xffffffffu, s1s, msk);
        }
        l0r = l0r * f0 + s0s; l1r = l1r * f1 + s1s;
        m0r = mn0; m1r = mn1;
        #pragma unroll
        for (int dt = 0; dt < 16; dt++) {
            o[dt][0] *= f0; o[dt][1] *= f0;
            o[dt][2] *= f1; o[dt][3] *= f1;
        }

        #pragma unroll
        for (int kks = 0; kks < 4; kks++) {
            uint32_t pha[4], pla[4];
            pha[0] = pack_hi2(sc[2*kks][0],   sc[2*kks][1]);
            pla[0] = pack_lo2(sc[2*kks][0],   sc[2*kks][1],   pha[0]);
            pha[1] = pack_hi2(sc[2*kks][2],   sc[2*kks][3]);
            pla[1] = pack_lo2(sc[2*kks][2],   sc[2*kks][3],   pha[1]);
            pha[2] = pack_hi2(sc[2*kks+1][0], sc[2*kks+1][1]);
            pla[2] = pack_lo2(sc[2*kks+1][0], sc[2*kks+1][1], pha[2]);
            pha[3] = pack_hi2(sc[2*kks+1][2], sc[2*kks+1][3]);
            pla[3] = pack_lo2(sc[2*kks+1][2], sc[2*kks+1][3], pha[3]);
            #pragma unroll
            for (int dt = 0; dt < 16; dt++) {
                const int br = (dt * 8 + g) * VS + kks * 16 + 2 * tig;
                uint32_t bh[2], bl[2];
                bh[0] = *reinterpret_cast<const uint32_t*>(&VTh[br]);
                bh[1] = *reinterpret_cast<const uint32_t*>(&VTh[br + 8]);
                bl[0] = *reinterpret_cast<const uint32_t*>(&VTl[br]);
                bl[1] = *reinterpret_cast<const uint32_t*>(&VTl[br + 8]);
                mma16816(o[dt], pha, bh);
                mma16816(o[dt], pha, bl);
                mma16816(o[dt], pla, bh);
            }
        }
    }

    const float inv0 = 1.f / l0r, inv1 = 1.f / l1r;
    const int row0 = t0 + wm * 16 + g;
    #pragma unroll
    for (int dt = 0; dt < 16; dt++) {
        int d = dt * 8 + 2 * tig;
        size_t b0 = ((size_t)(b * TT + row0) * HH + h) * DD + d;
        size_t b1 = ((size_t)(b * TT + row0 + 8) * HH + h) * DD + d;
        uint32_t h0 = pack_hi2(o[dt][0] * inv0, o[dt][1] * inv0);
        uint32_t l0 = pack_lo2(o[dt][0] * inv0, o[dt][1] * inv0, h0);
        uint32_t h1 = pack_hi2(o[dt][2] * inv1, o[dt][3] * inv1);
        uint32_t l1 = pack_lo2(o[dt][2] * inv1, o[dt][3] * inv1, h1);
        *reinterpret_cast<uint32_t*>(&yh[b0]) = h0;
        *reinterpret_cast<uint32_t*>(&yl[b0]) = l0;
        *reinterpret_cast<uint32_t*>(&yh[b1]) = h1;
        *reinterpret_cast<uint32_t*>(&yl[b1]) = l1;
    }
}

// ---------------------------------------------------------------------------
// Launch (single stream; no fork — fork/join suspected of invalidating
// graph capture and removed per contingency)
// ---------------------------------------------------------------------------
extern "C" void kernel_launch(void* const* d_in, const int* in_sizes, int n_in,
                              void* d_out, int out_size)
{
    const float* x      = (const float*)d_in[0];
    const float* w_q    = (const float*)d_in[1];
    const float* w_k    = (const float*)d_in[2];
    const float* w_v    = (const float*)d_in[3];
    const float* w_proj = (const float*)d_in[4];
    const float* w_dk   = (const float*)d_in[5];
    const float* w_dv   = (const float*)d_in[6];
    const float* fcos   = (const float*)d_in[7];
    const float* fsin   = (const float*)d_in[8];

    float* out    = (float*)d_out;
    float* out_y  = out;
    float* out_kw = out + (size_t)BB * TT * CCH;
    float* out_vw = out_kw + (size_t)BB * HKK * TT * DD;

    static float *pq = nullptr, *pk = nullptr, *pv = nullptr;
    static __nv_bfloat16 *xh, *xl, *yh, *yl, *wh, *wl;
    if (!pq) {
        cudaGetSymbolAddress((void**)&pq, g_q);
        cudaGetSymbolAddress((void**)&pk, g_k);
        cudaGetSymbolAddress((void**)&pv, g_v);
        cudaGetSymbolAddress((void**)&xh, g_xh);
        cudaGetSymbolAddress((void**)&xl, g_xl);
        cudaGetSymbolAddress((void**)&yh, g_yh);
        cudaGetSymbolAddress((void**)&yl, g_yl);
        cudaGetSymbolAddress((void**)&wh, g_wh);
        cudaGetSymbolAddress((void**)&wl, g_wl);
        cudaFuncSetAttribute(attn_mma,
                             cudaFuncAttributeMaxDynamicSharedMemorySize, ATT_SMEM);
        cudaFuncSetAttribute(gemm_mma<0>,
                             cudaFuncAttributeMaxDynamicSharedMemorySize, GEMM_DYN);
        cudaFuncSetAttribute(gemm_mma<1>,
                             cudaFuncAttributeMaxDynamicSharedMemorySize, GEMM_DYN);
        cudaFuncSetAttribute(gemm_mma<3>,
                             cudaFuncAttributeMaxDynamicSharedMemorySize, GEMM_DYN);
    }

    dim3 tb(32, 8);
    dim3 blk(256);
    const int MT = MR / 128;

    // 1) prep: split x, transpose weights (merged kvdd)
    split_f32<<<(MR * CCH / 4 + 255) / 256, 256>>>(x, xh, xl, MR * CCH / 4);
    transpose_w<<<dim3(CCH / 32, CCH / 32), tb>>>(w_q, wh + WQ_OFF, wl + WQ_OFF, CCH, CCH);
    transpose_kvdd<<<dim3(64, CCH / 32), tb>>>(w_k, w_v, w_dk, w_dv, wh + WK_OFF, wl + WK_OFF);
    transpose_w<<<dim3(CCH / 32, CCH / 32), tb>>>(w_proj, wh + WP_OFF, wl + WP_OFF, CCH, CCH);

    // 2) projections (sequential, single stream)
    gemm_mma<1><<<dim3(16, MT), blk, GEMM_DYN>>>(xh, xl, wh + WQ_OFF, wl + WQ_OFF,
                                                 pq, 0, 0, 0, CCH, fcos, fsin);
    gemm_mma<3><<<dim3(16, MT), blk, GEMM_DYN>>>(xh, xl, wh + WK_OFF, wl + WK_OFF,
                                                 pk, pv, out_kw, out_vw, 2048, fcos, fsin);

    // 3) attention (HMMA bf16x3) -> y bf16 hi/lo
    attn_mma<<<dim3(TT / 128, HH, BB), blk, ATT_SMEM>>>(pq, pk, pv, yh, yl);
    // 4) output projection
    gemm_mma<0><<<dim3(16, MT), blk, GEMM_DYN>>>(yh, yl, wh + WP_OFF, wl + WP_OFF,
                                                 out_y, 0, 0, 0, CCH, 0, 0);
}